// round 1
// baseline (speedup 1.0000x reference)
#include <cuda_runtime.h>
#include <math.h>

#define NB 4096      // batch
#define ND 1024      // feature dim
#define NH 2048      // hidden
#define NC 1000      // classes
#define NF 32        // var features

// ---------------- scratch (static device globals; no allocations) ----------
__device__ float g_means[NB * NF];
__device__ float g_combined[(size_t)NB * ND];
__device__ float g_hidden[(size_t)NB * NH];
__device__ float g_logits[(size_t)NB * NC];
__device__ float g_rowloss[NB];
__device__ float g_rowcorrect[NB];
__device__ float g_rowsq[NB];
__device__ int   g_starts[NB + 1];

// ---------------- 1. segment starts via binary search (ids are sorted) -----
__global__ void k_starts(const int* __restrict__ seg, int T) {
    int b = blockIdx.x * blockDim.x + threadIdx.x;
    if (b > NB) return;
    int lo = 0, hi = T;
    while (lo < hi) {
        int mid = (lo + hi) >> 1;
        if (seg[mid] < b) lo = mid + 1; else hi = mid;
    }
    g_starts[b] = lo;
}

// ---------------- 2. per-segment mean (one block per segment, no atomics) --
__global__ void k_means(const float* __restrict__ vf) {
    int b = blockIdx.x;
    int start = g_starts[b], end = g_starts[b + 1];
    int tid = threadIdx.x;          // 256 threads
    int j = tid & 7;                // float4 column group (8 * 4 = 32 cols)
    int r = tid >> 3;               // row offset 0..31
    float4 acc = make_float4(0.f, 0.f, 0.f, 0.f);
    for (int row = start + r; row < end; row += 32) {
        float4 v = *(const float4*)(vf + (size_t)row * NF + j * 4);
        acc.x += v.x; acc.y += v.y; acc.z += v.z; acc.w += v.w;
    }
    __shared__ float4 s[256];
    s[tid] = acc;
    __syncthreads();
    for (int off = 128; off >= 8; off >>= 1) {
        if (tid < off) {
            float4 o = s[tid + off];
            float4 m = s[tid];
            m.x += o.x; m.y += o.y; m.z += o.z; m.w += o.w;
            s[tid] = m;
        }
        __syncthreads();
    }
    if (tid < 8) {
        float inv = 1.0f / fmaxf((float)(end - start), 1.0f);
        float4 m = s[tid];
        m.x *= inv; m.y *= inv; m.z *= inv; m.w *= inv;
        *(float4*)(g_means + (size_t)b * NF + tid * 4) = m;
    }
}

// ---------------- 3. combined = feature + means @ Wv^T + bv ----------------
// grid: (ND/64, NB/128), 256 threads
__global__ void k_combined(const float* __restrict__ feat,
                           const float* __restrict__ Wv,
                           const float* __restrict__ bv) {
    __shared__ float wv_s[NF][64];    // [f][d]
    __shared__ float me_s[NF][128];   // [f][b]
    int d0 = blockIdx.x * 64, b0 = blockIdx.y * 128;
    int tid = threadIdx.x;

    for (int idx = tid; idx < 64 * 8; idx += 256) {
        int dd = idx >> 3, fg = (idx & 7) * 4;
        float4 v = *(const float4*)(Wv + (size_t)(d0 + dd) * NF + fg);
        wv_s[fg + 0][dd] = v.x; wv_s[fg + 1][dd] = v.y;
        wv_s[fg + 2][dd] = v.z; wv_s[fg + 3][dd] = v.w;
    }
    for (int idx = tid; idx < 128 * 8; idx += 256) {
        int bb = idx >> 3, fg = (idx & 7) * 4;
        float4 v = *(const float4*)(g_means + (size_t)(b0 + bb) * NF + fg);
        me_s[fg + 0][bb] = v.x; me_s[fg + 1][bb] = v.y;
        me_s[fg + 2][bb] = v.z; me_s[fg + 3][bb] = v.w;
    }
    __syncthreads();

    int tx = tid & 15, ty = tid >> 4;   // tx -> 4 d-cols, ty -> 8 b-rows
    float acc[8][4];
    #pragma unroll
    for (int r = 0; r < 8; r++)
        #pragma unroll
        for (int c = 0; c < 4; c++) acc[r][c] = 0.f;

    #pragma unroll 4
    for (int f = 0; f < NF; f++) {
        float w[4], m[8];
        #pragma unroll
        for (int c = 0; c < 4; c++) w[c] = wv_s[f][tx * 4 + c];
        #pragma unroll
        for (int r = 0; r < 8; r++) m[r] = me_s[f][ty * 8 + r];
        #pragma unroll
        for (int r = 0; r < 8; r++)
            #pragma unroll
            for (int c = 0; c < 4; c++) acc[r][c] += m[r] * w[c];
    }

    int d = d0 + tx * 4;
    float4 bvv = *(const float4*)(bv + d);
    #pragma unroll
    for (int r = 0; r < 8; r++) {
        int b = b0 + ty * 8 + r;
        float4 fv = *(const float4*)(feat + (size_t)b * ND + d);
        float4 o;
        o.x = fv.x + bvv.x + acc[r][0];
        o.y = fv.y + bvv.y + acc[r][1];
        o.z = fv.z + bvv.z + acc[r][2];
        o.w = fv.w + bvv.w + acc[r][3];
        *(float4*)(g_combined + (size_t)b * ND + d) = o;
    }
}

// ---------------- 4. tiled SGEMM-NT: C[m,n] = sum_k A[m,k]*B[n,k] + bias ---
// BM=BN=128, BK=16, 256 threads, 8x8 per-thread tile. M % 128 == 0 required.
template <bool RELU>
__global__ void k_sgemm_nt(const float* __restrict__ A,
                           const float* __restrict__ Bm,
                           const float* __restrict__ bias,
                           float* __restrict__ C,
                           int N, int K, int ldc) {
    __shared__ float As[16][128];
    __shared__ float Bs[16][128];
    int bm = blockIdx.y * 128, bn = blockIdx.x * 128;
    int tid = threadIdx.x;
    int lrow = tid >> 2;          // 0..63
    int lcol = (tid & 3) * 4;     // 0,4,8,12
    int tx = tid & 15, ty = tid >> 4;

    float acc[8][8];
    #pragma unroll
    for (int i = 0; i < 8; i++)
        #pragma unroll
        for (int j = 0; j < 8; j++) acc[i][j] = 0.f;

    for (int k0 = 0; k0 < K; k0 += 16) {
        #pragma unroll
        for (int h = 0; h < 2; h++) {
            int m = lrow + h * 64;
            float4 v = *(const float4*)(A + (size_t)(bm + m) * K + k0 + lcol);
            As[lcol + 0][m] = v.x; As[lcol + 1][m] = v.y;
            As[lcol + 2][m] = v.z; As[lcol + 3][m] = v.w;
        }
        #pragma unroll
        for (int h = 0; h < 2; h++) {
            int n = lrow + h * 64;
            float4 v = make_float4(0.f, 0.f, 0.f, 0.f);
            if (bn + n < N)
                v = *(const float4*)(Bm + (size_t)(bn + n) * K + k0 + lcol);
            Bs[lcol + 0][n] = v.x; Bs[lcol + 1][n] = v.y;
            Bs[lcol + 2][n] = v.z; Bs[lcol + 3][n] = v.w;
        }
        __syncthreads();

        #pragma unroll
        for (int k = 0; k < 16; k++) {
            float ar[8], br[8];
            *(float4*)(ar)     = *(const float4*)(&As[k][ty * 8]);
            *(float4*)(ar + 4) = *(const float4*)(&As[k][ty * 8 + 4]);
            *(float4*)(br)     = *(const float4*)(&Bs[k][tx * 8]);
            *(float4*)(br + 4) = *(const float4*)(&Bs[k][tx * 8 + 4]);
            #pragma unroll
            for (int i = 0; i < 8; i++)
                #pragma unroll
                for (int j = 0; j < 8; j++)
                    acc[i][j] += ar[i] * br[j];
        }
        __syncthreads();
    }

    // epilogue: bias (+relu), column-guarded for N=1000
    #pragma unroll
    for (int i = 0; i < 8; i++) {
        int m = bm + ty * 8 + i;
        #pragma unroll
        for (int jj = 0; jj < 2; jj++) {
            int n = bn + tx * 8 + jj * 4;
            if (n < N) {
                float4 bb = *(const float4*)(bias + n);
                float4 o;
                o.x = acc[i][jj * 4 + 0] + bb.x;
                o.y = acc[i][jj * 4 + 1] + bb.y;
                o.z = acc[i][jj * 4 + 2] + bb.z;
                o.w = acc[i][jj * 4 + 3] + bb.w;
                if (RELU) {
                    o.x = fmaxf(o.x, 0.f); o.y = fmaxf(o.y, 0.f);
                    o.z = fmaxf(o.z, 0.f); o.w = fmaxf(o.w, 0.f);
                }
                *(float4*)(C + (size_t)m * ldc + n) = o;
            }
        }
    }
}

// ---------------- 5. scalar head: (hidden @ Ws^T + bs - tgt)^2 -------------
__global__ void k_scalar(const float* __restrict__ Ws,
                         const float* __restrict__ bs,
                         const float* __restrict__ tgt) {
    int b = blockIdx.x, tid = threadIdx.x;   // 256 threads
    float a = 0.f;
    for (int h4 = tid; h4 < NH / 4; h4 += 256) {
        float4 hv = *(const float4*)(g_hidden + (size_t)b * NH + h4 * 4);
        float4 wv = *(const float4*)(Ws + h4 * 4);
        a += hv.x * wv.x + hv.y * wv.y + hv.z * wv.z + hv.w * wv.w;
    }
    __shared__ float s[256];
    s[tid] = a; __syncthreads();
    for (int off = 128; off > 0; off >>= 1) {
        if (tid < off) s[tid] += s[tid + off];
        __syncthreads();
    }
    if (tid == 0) {
        float sc = s[0] + bs[0];
        float d = sc - tgt[b];
        g_rowsq[b] = d * d;
    }
}

// ---------------- 6. per-row log-softmax CE + argmax -----------------------
__global__ void k_softmax(const int* __restrict__ tgt) {
    int b = blockIdx.x, tid = threadIdx.x;  // 256 threads
    const float* row = g_logits + (size_t)b * NC;

    float vmax = -INFINITY; int vidx = 0x7fffffff;
    for (int c = tid; c < NC; c += 256) {
        float v = row[c];
        if (v > vmax) { vmax = v; vidx = c; }
    }
    // warp argmax reduce (tie -> smaller index, matches jnp first-occurrence)
    for (int o = 16; o; o >>= 1) {
        float ov = __shfl_down_sync(0xffffffffu, vmax, o);
        int   oi = __shfl_down_sync(0xffffffffu, vidx, o);
        if (ov > vmax || (ov == vmax && oi < vidx)) { vmax = ov; vidx = oi; }
    }
    __shared__ float sv[8]; __shared__ int si[8];
    if ((tid & 31) == 0) { sv[tid >> 5] = vmax; si[tid >> 5] = vidx; }
    __syncthreads();
    __shared__ float bmax_s; __shared__ int bidx_s;
    if (tid == 0) {
        float m = sv[0]; int ix = si[0];
        for (int w = 1; w < 8; w++)
            if (sv[w] > m || (sv[w] == m && si[w] < ix)) { m = sv[w]; ix = si[w]; }
        bmax_s = m; bidx_s = ix;
    }
    __syncthreads();
    float bmax = bmax_s;

    float se = 0.f;
    for (int c = tid; c < NC; c += 256) se += expf(row[c] - bmax);
    for (int o = 16; o; o >>= 1) se += __shfl_down_sync(0xffffffffu, se, o);
    __shared__ float ss[8];
    if ((tid & 31) == 0) ss[tid >> 5] = se;
    __syncthreads();
    if (tid == 0) {
        float tot = 0.f;
        for (int w = 0; w < 8; w++) tot += ss[w];
        int t = tgt[b];
        float lp = row[t] - bmax - logf(tot);
        g_rowloss[b] = -lp;
        g_rowcorrect[b] = (bidx_s == t) ? 1.0f : 0.0f;
    }
}

// ---------------- 7. final deterministic reduce -----------------------------
__global__ void k_final(float* __restrict__ out) {
    int tid = threadIdx.x;   // 1024 threads
    float l = 0.f, c = 0.f, q = 0.f;
    for (int i = tid; i < NB; i += 1024) {
        l += g_rowloss[i]; c += g_rowcorrect[i]; q += g_rowsq[i];
    }
    __shared__ float sl[1024], sc[1024], sq[1024];
    sl[tid] = l; sc[tid] = c; sq[tid] = q;
    __syncthreads();
    for (int off = 512; off > 0; off >>= 1) {
        if (tid < off) {
            sl[tid] += sl[tid + off];
            sc[tid] += sc[tid + off];
            sq[tid] += sq[tid + off];
        }
        __syncthreads();
    }
    if (tid == 0) {
        float lv = sl[0] / (float)NB;
        float ls = sq[0] / (float)NB;
        float ac = sc[0] / (float)NB;
        out[0] = lv + ls;   // total_loss
        out[1] = lv;        // loss_vector
        out[2] = ls;        // loss_scalar
        out[3] = ac;        // acc
    }
}

// ---------------- launch ----------------------------------------------------
extern "C" void kernel_launch(void* const* d_in, const int* in_sizes, int n_in,
                              void* d_out, int out_size) {
    const float* feature = (const float*)d_in[0];
    const float* var_flat = (const float*)d_in[1];
    const int*   seg      = (const int*)d_in[2];
    const int*   tgt_vec  = (const int*)d_in[3];
    const float* tgt_sca  = (const float*)d_in[4];
    const float* Wv = (const float*)d_in[5];
    const float* bv = (const float*)d_in[6];
    const float* W1 = (const float*)d_in[7];
    const float* b1 = (const float*)d_in[8];
    const float* W2 = (const float*)d_in[9];
    const float* b2 = (const float*)d_in[10];
    const float* Ws = (const float*)d_in[11];
    const float* bs = (const float*)d_in[12];
    float* out = (float*)d_out;

    int T = in_sizes[1] / NF;

    // 1. segment starts
    k_starts<<<(NB + 1 + 255) / 256, 256>>>(seg, T);
    // 2. segment means
    k_means<<<NB, 256>>>(var_flat);
    // 3. combined = feature + means @ Wv^T + bv
    {
        dim3 g(ND / 64, NB / 128);
        k_combined<<<g, 256>>>(feature, Wv, bv);
    }
    // 4. hidden = relu(combined @ W1^T + b1)   [4096 x 2048]
    {
        float* combined_p; float* hidden_p;
        cudaGetSymbolAddress((void**)&combined_p, g_combined);
        cudaGetSymbolAddress((void**)&hidden_p, g_hidden);
        dim3 g(NH / 128, NB / 128);
        k_sgemm_nt<true><<<g, 256>>>(combined_p, W1, b1, hidden_p, NH, ND, NH);
    }
    // 5. logits = hidden @ W2^T + b2           [4096 x 1000]
    {
        float* hidden_p; float* logits_p;
        cudaGetSymbolAddress((void**)&hidden_p, g_hidden);
        cudaGetSymbolAddress((void**)&logits_p, g_logits);
        dim3 g((NC + 127) / 128, NB / 128);
        k_sgemm_nt<false><<<g, 256>>>(hidden_p, W2, b2, logits_p, NC, NH, NC);
    }
    // 6. scalar head MSE per row
    k_scalar<<<NB, 256>>>(Ws, bs, tgt_sca);
    // 7. softmax CE + argmax per row
    k_softmax<<<NB, 256>>>(tgt_vec);
    // 8. final reduce -> 4 outputs
    k_final<<<1, 1024>>>(out);
}

// round 2
// speedup vs baseline: 1.0006x; 1.0006x over previous
#include <cuda_runtime.h>
#include <math.h>

#define NB 4096      // batch
#define ND 1024      // feature dim
#define NH 2048      // hidden
#define NC 1000      // classes
#define NF 32        // var features

// ---------------- scratch (static device globals; no allocations) ----------
__device__ float g_means[NB * NF];
__device__ float g_combined[(size_t)NB * ND];
__device__ float g_hidden[(size_t)NB * NH];
__device__ float g_logits[(size_t)NB * NC];
__device__ float g_rowloss[NB];
__device__ float g_rowcorrect[NB];
__device__ float g_rowsq[NB];
__device__ int   g_starts[NB + 1];

// ---------------- 1. segment starts via binary search (ids are sorted) -----
__global__ void k_starts(const int* __restrict__ seg, int T) {
    int b = blockIdx.x * blockDim.x + threadIdx.x;
    if (b > NB) return;
    int lo = 0, hi = T;
    while (lo < hi) {
        int mid = (lo + hi) >> 1;
        if (seg[mid] < b) lo = mid + 1; else hi = mid;
    }
    g_starts[b] = lo;
}

// ---------------- 2. per-segment mean (one block per segment, no atomics) --
__global__ void k_means(const float* __restrict__ vf) {
    int b = blockIdx.x;
    int start = g_starts[b], end = g_starts[b + 1];
    int tid = threadIdx.x;          // 256 threads
    int j = tid & 7;                // float4 column group (8 * 4 = 32 cols)
    int r = tid >> 3;               // row offset 0..31
    float4 acc = make_float4(0.f, 0.f, 0.f, 0.f);
    for (int row = start + r; row < end; row += 32) {
        float4 v = *(const float4*)(vf + (size_t)row * NF + j * 4);
        acc.x += v.x; acc.y += v.y; acc.z += v.z; acc.w += v.w;
    }
    __shared__ float4 s[256];
    s[tid] = acc;
    __syncthreads();
    for (int off = 128; off >= 8; off >>= 1) {
        if (tid < off) {
            float4 o = s[tid + off];
            float4 m = s[tid];
            m.x += o.x; m.y += o.y; m.z += o.z; m.w += o.w;
            s[tid] = m;
        }
        __syncthreads();
    }
    if (tid < 8) {
        float inv = 1.0f / fmaxf((float)(end - start), 1.0f);
        float4 m = s[tid];
        m.x *= inv; m.y *= inv; m.z *= inv; m.w *= inv;
        *(float4*)(g_means + (size_t)b * NF + tid * 4) = m;
    }
}

// ---------------- 3. combined = feature + means @ Wv^T + bv ----------------
// grid: (ND/64, NB/128), 256 threads
__global__ void k_combined(const float* __restrict__ feat,
                           const float* __restrict__ Wv,
                           const float* __restrict__ bv) {
    __shared__ float wv_s[NF][64];    // [f][d]
    __shared__ float me_s[NF][128];   // [f][b]
    int d0 = blockIdx.x * 64, b0 = blockIdx.y * 128;
    int tid = threadIdx.x;

    for (int idx = tid; idx < 64 * 8; idx += 256) {
        int dd = idx >> 3, fg = (idx & 7) * 4;
        float4 v = *(const float4*)(Wv + (size_t)(d0 + dd) * NF + fg);
        wv_s[fg + 0][dd] = v.x; wv_s[fg + 1][dd] = v.y;
        wv_s[fg + 2][dd] = v.z; wv_s[fg + 3][dd] = v.w;
    }
    for (int idx = tid; idx < 128 * 8; idx += 256) {
        int bb = idx >> 3, fg = (idx & 7) * 4;
        float4 v = *(const float4*)(g_means + (size_t)(b0 + bb) * NF + fg);
        me_s[fg + 0][bb] = v.x; me_s[fg + 1][bb] = v.y;
        me_s[fg + 2][bb] = v.z; me_s[fg + 3][bb] = v.w;
    }
    __syncthreads();

    int tx = tid & 15, ty = tid >> 4;   // tx -> 4 d-cols, ty -> 8 b-rows
    float acc[8][4];
    #pragma unroll
    for (int r = 0; r < 8; r++)
        #pragma unroll
        for (int c = 0; c < 4; c++) acc[r][c] = 0.f;

    #pragma unroll 4
    for (int f = 0; f < NF; f++) {
        float w[4], m[8];
        #pragma unroll
        for (int c = 0; c < 4; c++) w[c] = wv_s[f][tx * 4 + c];
        #pragma unroll
        for (int r = 0; r < 8; r++) m[r] = me_s[f][ty * 8 + r];
        #pragma unroll
        for (int r = 0; r < 8; r++)
            #pragma unroll
            for (int c = 0; c < 4; c++) acc[r][c] += m[r] * w[c];
    }

    int d = d0 + tx * 4;
    float4 bvv = *(const float4*)(bv + d);
    #pragma unroll
    for (int r = 0; r < 8; r++) {
        int b = b0 + ty * 8 + r;
        float4 fv = *(const float4*)(feat + (size_t)b * ND + d);
        float4 o;
        o.x = fv.x + bvv.x + acc[r][0];
        o.y = fv.y + bvv.y + acc[r][1];
        o.z = fv.z + bvv.z + acc[r][2];
        o.w = fv.w + bvv.w + acc[r][3];
        *(float4*)(g_combined + (size_t)b * ND + d) = o;
    }
}

// ---------------- 4. tiled SGEMM-NT: C[m,n] = sum_k A[m,k]*B[n,k] + bias ---
// BM=BN=128, BK=16, 256 threads, 8x8 per-thread tile. M % 128 == 0 required.
template <bool RELU>
__global__ void k_sgemm_nt(const float* __restrict__ A,
                           const float* __restrict__ Bm,
                           const float* __restrict__ bias,
                           float* __restrict__ C,
                           int N, int K, int ldc) {
    __shared__ float As[16][128];
    __shared__ float Bs[16][128];
    int bm = blockIdx.y * 128, bn = blockIdx.x * 128;
    int tid = threadIdx.x;
    int lrow = tid >> 2;          // 0..63
    int lcol = (tid & 3) * 4;     // 0,4,8,12
    int tx = tid & 15, ty = tid >> 4;

    float acc[8][8];
    #pragma unroll
    for (int i = 0; i < 8; i++)
        #pragma unroll
        for (int j = 0; j < 8; j++) acc[i][j] = 0.f;

    for (int k0 = 0; k0 < K; k0 += 16) {
        #pragma unroll
        for (int h = 0; h < 2; h++) {
            int m = lrow + h * 64;
            float4 v = *(const float4*)(A + (size_t)(bm + m) * K + k0 + lcol);
            As[lcol + 0][m] = v.x; As[lcol + 1][m] = v.y;
            As[lcol + 2][m] = v.z; As[lcol + 3][m] = v.w;
        }
        #pragma unroll
        for (int h = 0; h < 2; h++) {
            int n = lrow + h * 64;
            float4 v = make_float4(0.f, 0.f, 0.f, 0.f);
            if (bn + n < N)
                v = *(const float4*)(Bm + (size_t)(bn + n) * K + k0 + lcol);
            Bs[lcol + 0][n] = v.x; Bs[lcol + 1][n] = v.y;
            Bs[lcol + 2][n] = v.z; Bs[lcol + 3][n] = v.w;
        }
        __syncthreads();

        #pragma unroll
        for (int k = 0; k < 16; k++) {
            float ar[8], br[8];
            *(float4*)(ar)     = *(const float4*)(&As[k][ty * 8]);
            *(float4*)(ar + 4) = *(const float4*)(&As[k][ty * 8 + 4]);
            *(float4*)(br)     = *(const float4*)(&Bs[k][tx * 8]);
            *(float4*)(br + 4) = *(const float4*)(&Bs[k][tx * 8 + 4]);
            #pragma unroll
            for (int i = 0; i < 8; i++)
                #pragma unroll
                for (int j = 0; j < 8; j++)
                    acc[i][j] += ar[i] * br[j];
        }
        __syncthreads();
    }

    // epilogue: bias (+relu), column-guarded for N=1000
    #pragma unroll
    for (int i = 0; i < 8; i++) {
        int m = bm + ty * 8 + i;
        #pragma unroll
        for (int jj = 0; jj < 2; jj++) {
            int n = bn + tx * 8 + jj * 4;
            if (n < N) {
                float4 bb = *(const float4*)(bias + n);
                float4 o;
                o.x = acc[i][jj * 4 + 0] + bb.x;
                o.y = acc[i][jj * 4 + 1] + bb.y;
                o.z = acc[i][jj * 4 + 2] + bb.z;
                o.w = acc[i][jj * 4 + 3] + bb.w;
                if (RELU) {
                    o.x = fmaxf(o.x, 0.f); o.y = fmaxf(o.y, 0.f);
                    o.z = fmaxf(o.z, 0.f); o.w = fmaxf(o.w, 0.f);
                }
                *(float4*)(C + (size_t)m * ldc + n) = o;
            }
        }
    }
}

// ---------------- 5. scalar head: (hidden @ Ws^T + bs - tgt)^2 -------------
__global__ void k_scalar(const float* __restrict__ Ws,
                         const float* __restrict__ bs,
                         const float* __restrict__ tgt) {
    int b = blockIdx.x, tid = threadIdx.x;   // 256 threads
    float a = 0.f;
    for (int h4 = tid; h4 < NH / 4; h4 += 256) {
        float4 hv = *(const float4*)(g_hidden + (size_t)b * NH + h4 * 4);
        float4 wv = *(const float4*)(Ws + h4 * 4);
        a += hv.x * wv.x + hv.y * wv.y + hv.z * wv.z + hv.w * wv.w;
    }
    __shared__ float s[256];
    s[tid] = a; __syncthreads();
    for (int off = 128; off > 0; off >>= 1) {
        if (tid < off) s[tid] += s[tid + off];
        __syncthreads();
    }
    if (tid == 0) {
        float sc = s[0] + bs[0];
        float d = sc - tgt[b];
        g_rowsq[b] = d * d;
    }
}

// ---------------- 6. per-row log-softmax CE + argmax -----------------------
__global__ void k_softmax(const int* __restrict__ tgt) {
    int b = blockIdx.x, tid = threadIdx.x;  // 256 threads
    const float* row = g_logits + (size_t)b * NC;

    float vmax = -INFINITY; int vidx = 0x7fffffff;
    for (int c = tid; c < NC; c += 256) {
        float v = row[c];
        if (v > vmax) { vmax = v; vidx = c; }
    }
    // warp argmax reduce (tie -> smaller index, matches jnp first-occurrence)
    for (int o = 16; o; o >>= 1) {
        float ov = __shfl_down_sync(0xffffffffu, vmax, o);
        int   oi = __shfl_down_sync(0xffffffffu, vidx, o);
        if (ov > vmax || (ov == vmax && oi < vidx)) { vmax = ov; vidx = oi; }
    }
    __shared__ float sv[8]; __shared__ int si[8];
    if ((tid & 31) == 0) { sv[tid >> 5] = vmax; si[tid >> 5] = vidx; }
    __syncthreads();
    __shared__ float bmax_s; __shared__ int bidx_s;
    if (tid == 0) {
        float m = sv[0]; int ix = si[0];
        for (int w = 1; w < 8; w++)
            if (sv[w] > m || (sv[w] == m && si[w] < ix)) { m = sv[w]; ix = si[w]; }
        bmax_s = m; bidx_s = ix;
    }
    __syncthreads();
    float bmax = bmax_s;

    float se = 0.f;
    for (int c = tid; c < NC; c += 256) se += expf(row[c] - bmax);
    for (int o = 16; o; o >>= 1) se += __shfl_down_sync(0xffffffffu, se, o);
    __shared__ float ss[8];
    if ((tid & 31) == 0) ss[tid >> 5] = se;
    __syncthreads();
    if (tid == 0) {
        float tot = 0.f;
        for (int w = 0; w < 8; w++) tot += ss[w];
        int t = tgt[b];
        float lp = row[t] - bmax - logf(tot);
        g_rowloss[b] = -lp;
        g_rowcorrect[b] = (bidx_s == t) ? 1.0f : 0.0f;
    }
}

// ---------------- 7. final deterministic reduce -----------------------------
__global__ void k_final(float* __restrict__ out) {
    int tid = threadIdx.x;   // 1024 threads
    float l = 0.f, c = 0.f, q = 0.f;
    for (int i = tid; i < NB; i += 1024) {
        l += g_rowloss[i]; c += g_rowcorrect[i]; q += g_rowsq[i];
    }
    __shared__ float sl[1024], sc[1024], sq[1024];
    sl[tid] = l; sc[tid] = c; sq[tid] = q;
    __syncthreads();
    for (int off = 512; off > 0; off >>= 1) {
        if (tid < off) {
            sl[tid] += sl[tid + off];
            sc[tid] += sc[tid + off];
            sq[tid] += sq[tid + off];
        }
        __syncthreads();
    }
    if (tid == 0) {
        float lv = sl[0] / (float)NB;
        float ls = sq[0] / (float)NB;
        float ac = sc[0] / (float)NB;
        out[0] = lv + ls;   // total_loss
        out[1] = lv;        // loss_vector
        out[2] = ls;        // loss_scalar
        out[3] = ac;        // acc
    }
}

// ---------------- launch ----------------------------------------------------
extern "C" void kernel_launch(void* const* d_in, const int* in_sizes, int n_in,
                              void* d_out, int out_size) {
    const float* feature = (const float*)d_in[0];
    const float* var_flat = (const float*)d_in[1];
    const int*   seg      = (const int*)d_in[2];
    const int*   tgt_vec  = (const int*)d_in[3];
    const float* tgt_sca  = (const float*)d_in[4];
    const float* Wv = (const float*)d_in[5];
    const float* bv = (const float*)d_in[6];
    const float* W1 = (const float*)d_in[7];
    const float* b1 = (const float*)d_in[8];
    const float* W2 = (const float*)d_in[9];
    const float* b2 = (const float*)d_in[10];
    const float* Ws = (const float*)d_in[11];
    const float* bs = (const float*)d_in[12];
    float* out = (float*)d_out;

    int T = in_sizes[1] / NF;

    // 1. segment starts
    k_starts<<<(NB + 1 + 255) / 256, 256>>>(seg, T);
    // 2. segment means
    k_means<<<NB, 256>>>(var_flat);
    // 3. combined = feature + means @ Wv^T + bv
    {
        dim3 g(ND / 64, NB / 128);
        k_combined<<<g, 256>>>(feature, Wv, bv);
    }
    // 4. hidden = relu(combined @ W1^T + b1)   [4096 x 2048]
    {
        float* combined_p; float* hidden_p;
        cudaGetSymbolAddress((void**)&combined_p, g_combined);
        cudaGetSymbolAddress((void**)&hidden_p, g_hidden);
        dim3 g(NH / 128, NB / 128);
        k_sgemm_nt<true><<<g, 256>>>(combined_p, W1, b1, hidden_p, NH, ND, NH);
    }
    // 5. logits = hidden @ W2^T + b2           [4096 x 1000]
    {
        float* hidden_p; float* logits_p;
        cudaGetSymbolAddress((void**)&hidden_p, g_hidden);
        cudaGetSymbolAddress((void**)&logits_p, g_logits);
        dim3 g((NC + 127) / 128, NB / 128);
        k_sgemm_nt<false><<<g, 256>>>(hidden_p, W2, b2, logits_p, NC, NH, NC);
    }
    // 6. scalar head MSE per row
    k_scalar<<<NB, 256>>>(Ws, bs, tgt_sca);
    // 7. softmax CE + argmax per row
    k_softmax<<<NB, 256>>>(tgt_vec);
    // 8. final reduce -> 4 outputs
    k_final<<<1, 1024>>>(out);
}

// round 5
// speedup vs baseline: 2.3339x; 2.3325x over previous
#include <cuda_runtime.h>
#include <cuda_bf16.h>
#include <math.h>
#include <stdint.h>

#define NB 4096
#define ND 1024
#define NH 2048
#define NC 1000
#define NF 32
#define K1 (3*ND)   // 3072 split-cat K for GEMM1
#define K2 (3*NH)   // 6144 split-cat K for GEMM2

// ---------------- scratch ---------------------------------------------------
__device__ float g_means[NB * NF];
__device__ __align__(16) __nv_bfloat16 g_acat1[(size_t)NB * K1];
__device__ __align__(16) __nv_bfloat16 g_w1cat[(size_t)NH * K1];
__device__ __align__(16) __nv_bfloat16 g_hcat[(size_t)NB * K2];
__device__ __align__(16) __nv_bfloat16 g_w2cat[(size_t)NC * K2];
__device__ float g_logits[(size_t)NB * NC];
__device__ float g_rowloss[NB];
__device__ float g_rowcorrect[NB];
__device__ float g_rowsq[NB];
__device__ int   g_starts[NB + 1];

// ---------------- helpers ---------------------------------------------------
__device__ __forceinline__ uint32_t smem_u32(const void* p) {
    uint32_t a;
    asm("{ .reg .u64 t; cvta.to.shared.u64 t, %1; cvt.u32.u64 %0, t; }"
        : "=r"(a) : "l"(p));
    return a;
}

__device__ __forceinline__ void ldsm4(uint32_t& r0, uint32_t& r1, uint32_t& r2,
                                      uint32_t& r3, uint32_t a) {
    asm volatile("ldmatrix.sync.aligned.m8n8.x4.shared.b16 {%0,%1,%2,%3}, [%4];"
                 : "=r"(r0), "=r"(r1), "=r"(r2), "=r"(r3) : "r"(a));
}

__device__ __forceinline__ void mma16816(float* c, uint32_t a0, uint32_t a1,
                                         uint32_t a2, uint32_t a3,
                                         uint32_t b0, uint32_t b1) {
    asm volatile(
        "mma.sync.aligned.m16n8k16.row.col.f32.bf16.bf16.f32 "
        "{%0,%1,%2,%3}, {%4,%5,%6,%7}, {%8,%9}, {%0,%1,%2,%3};"
        : "+f"(c[0]), "+f"(c[1]), "+f"(c[2]), "+f"(c[3])
        : "r"(a0), "r"(a1), "r"(a2), "r"(a3), "r"(b0), "r"(b1));
}

#define CPA16(sa, ga, pbytes) \
    asm volatile("cp.async.cg.shared.global [%0], [%1], 16, %2;" \
                 :: "r"(sa), "l"(ga), "r"(pbytes))
#define CPA_COMMIT() asm volatile("cp.async.commit_group;" ::: "memory")

// ---------------- 1. segment starts -----------------------------------------
__global__ void k_starts(const int* __restrict__ seg, int T) {
    int b = blockIdx.x * blockDim.x + threadIdx.x;
    if (b > NB) return;
    int lo = 0, hi = T;
    while (lo < hi) { int m = (lo + hi) >> 1; if (seg[m] < b) lo = m + 1; else hi = m; }
    g_starts[b] = lo;
}

// ---------------- 2. per-segment mean ---------------------------------------
__global__ void k_means(const float* __restrict__ vf) {
    int b = blockIdx.x;
    int start = g_starts[b], end = g_starts[b + 1];
    int tid = threadIdx.x;
    int j = tid & 7, r = tid >> 3;
    float4 acc = make_float4(0.f, 0.f, 0.f, 0.f);
    for (int row = start + r; row < end; row += 32) {
        float4 v = *(const float4*)(vf + (size_t)row * NF + j * 4);
        acc.x += v.x; acc.y += v.y; acc.z += v.z; acc.w += v.w;
    }
    __shared__ float4 s[256];
    s[tid] = acc; __syncthreads();
    for (int off = 128; off >= 8; off >>= 1) {
        if (tid < off) {
            float4 o = s[tid + off]; float4 m = s[tid];
            m.x += o.x; m.y += o.y; m.z += o.z; m.w += o.w; s[tid] = m;
        }
        __syncthreads();
    }
    if (tid < 8) {
        float inv = 1.0f / fmaxf((float)(end - start), 1.0f);
        float4 m = s[tid];
        m.x *= inv; m.y *= inv; m.z *= inv; m.w *= inv;
        *(float4*)(g_means + (size_t)b * NF + tid * 4) = m;
    }
}

// ------- 3. weight fp32 -> bf16 3-seg B-pattern [hi, hi, lo] ----------------
__global__ void k_cvt_w(const float* __restrict__ W, __nv_bfloat16* __restrict__ out,
                        int R, int K) {
    int half = K >> 1;
    int idx = blockIdx.x * blockDim.x + threadIdx.x;
    if (idx >= R * half) return;
    int r = idx / half;
    int c = (idx - r * half) * 2;
    float2 v = *(const float2*)(W + (size_t)r * K + c);
    __nv_bfloat16 h0 = __float2bfloat16_rn(v.x), h1 = __float2bfloat16_rn(v.y);
    __nv_bfloat16 l0 = __float2bfloat16_rn(v.x - __bfloat162float(h0));
    __nv_bfloat16 l1 = __float2bfloat16_rn(v.y - __bfloat162float(h1));
    __nv_bfloat162 H, L; H.x = h0; H.y = h1; L.x = l0; L.y = l1;
    __nv_bfloat16* ob = out + (size_t)r * (3 * K) + c;
    *(__nv_bfloat162*)(ob)         = H;
    *(__nv_bfloat162*)(ob + K)     = H;
    *(__nv_bfloat162*)(ob + 2 * K) = L;
}

// ------- 4. combined = feature + means @ Wv^T + bv -> A-pattern [hi, lo, hi] -
__global__ void k_combined(const float* __restrict__ feat,
                           const float* __restrict__ Wv,
                           const float* __restrict__ bv) {
    __shared__ float wv_s[NF][64];
    __shared__ float me_s[NF][128];
    int d0 = blockIdx.x * 64, b0 = blockIdx.y * 128;
    int tid = threadIdx.x;
    for (int idx = tid; idx < 64 * 8; idx += 256) {
        int dd = idx >> 3, fg = (idx & 7) * 4;
        float4 v = *(const float4*)(Wv + (size_t)(d0 + dd) * NF + fg);
        wv_s[fg + 0][dd] = v.x; wv_s[fg + 1][dd] = v.y;
        wv_s[fg + 2][dd] = v.z; wv_s[fg + 3][dd] = v.w;
    }
    for (int idx = tid; idx < 128 * 8; idx += 256) {
        int bb = idx >> 3, fg = (idx & 7) * 4;
        float4 v = *(const float4*)(g_means + (size_t)(b0 + bb) * NF + fg);
        me_s[fg + 0][bb] = v.x; me_s[fg + 1][bb] = v.y;
        me_s[fg + 2][bb] = v.z; me_s[fg + 3][bb] = v.w;
    }
    __syncthreads();
    int tx = tid & 15, ty = tid >> 4;
    float acc[8][4];
    #pragma unroll
    for (int r = 0; r < 8; r++)
        #pragma unroll
        for (int c = 0; c < 4; c++) acc[r][c] = 0.f;
    #pragma unroll 4
    for (int f = 0; f < NF; f++) {
        float w[4], m[8];
        #pragma unroll
        for (int c = 0; c < 4; c++) w[c] = wv_s[f][tx * 4 + c];
        #pragma unroll
        for (int r = 0; r < 8; r++) m[r] = me_s[f][ty * 8 + r];
        #pragma unroll
        for (int r = 0; r < 8; r++)
            #pragma unroll
            for (int c = 0; c < 4; c++) acc[r][c] += m[r] * w[c];
    }
    int d = d0 + tx * 4;
    float4 bvv = *(const float4*)(bv + d);
    #pragma unroll
    for (int r = 0; r < 8; r++) {
        int b = b0 + ty * 8 + r;
        float4 fv = *(const float4*)(feat + (size_t)b * ND + d);
        float o[4] = { fv.x + bvv.x + acc[r][0], fv.y + bvv.y + acc[r][1],
                       fv.z + bvv.z + acc[r][2], fv.w + bvv.w + acc[r][3] };
        __nv_bfloat16* ob = g_acat1 + (size_t)b * K1 + d;
        #pragma unroll
        for (int p = 0; p < 2; p++) {
            __nv_bfloat16 h0 = __float2bfloat16_rn(o[p * 2]);
            __nv_bfloat16 h1 = __float2bfloat16_rn(o[p * 2 + 1]);
            __nv_bfloat16 l0 = __float2bfloat16_rn(o[p * 2] - __bfloat162float(h0));
            __nv_bfloat16 l1 = __float2bfloat16_rn(o[p * 2 + 1] - __bfloat162float(h1));
            __nv_bfloat162 H, L; H.x = h0; H.y = h1; L.x = l0; L.y = l1;
            *(__nv_bfloat162*)(ob + p * 2)          = H;
            *(__nv_bfloat162*)(ob + ND + p * 2)     = L;
            *(__nv_bfloat162*)(ob + 2 * ND + p * 2) = H;
        }
    }
}

// ------- 5. mma.sync GEMM: C = A @ B^T (+bias; relu+split or fp32 store) ----
// 128x128x64 tiles, 4-stage cp.async, ldmatrix, m16n8k16 bf16, fp32 accum.
// 8 warps as 2(m) x 4(n): warp tile 64x32.
template <bool HID>
__global__ void __launch_bounds__(256, 1)
k_gemm_mma(const __nv_bfloat16* __restrict__ A, const __nv_bfloat16* __restrict__ B,
           const float* __restrict__ bias, void* __restrict__ outp,
           int Kp, int Nrows, int NK) {
    extern __shared__ char dsm[];
    uint32_t raw = smem_u32(dsm);
    const uint32_t sm0 = (raw + 1023u) & ~1023u;

    const int tid = threadIdx.x, wid = tid >> 5, lane = tid & 31;
    const int wm = wid & 1, wn = wid >> 1;
    const int bm = blockIdx.y * 128, bn = blockIdx.x * 128;
    const size_t rowb = (size_t)Kp * 2;

    // loader lane mapping: row0 = tid>>3 (0..31), chunk s = tid&7
    const int lrow0 = tid >> 3;
    const int ls    = tid & 7;
    const uint32_t lsw = (uint32_t)((ls * 16) ^ ((lrow0 & 7) * 16));

    auto load_stage = [&](int slot, int kt) {
        uint32_t sb = sm0 + slot * 32768;
        int k0b = kt * 128;
        #pragma unroll
        for (int i = 0; i < 4; i++) {          // A: rows lrow0 + i*32
            int r = lrow0 + i * 32;
            uint32_t sa = sb + r * 128 + lsw;
            const char* g = (const char*)A + (size_t)(bm + r) * rowb + k0b + ls * 16;
            CPA16(sa, g, 16);
        }
        #pragma unroll
        for (int i = 0; i < 4; i++) {          // B: rows lrow0 + i*32
            int r = lrow0 + i * 32;
            int gr = bn + r;
            bool v = gr < Nrows;
            uint32_t sa = sb + 16384 + r * 128 + lsw;
            const char* g = (const char*)B + (size_t)(v ? gr : 0) * rowb + k0b + ls * 16;
            CPA16(sa, g, v ? 16 : 0);
        }
        CPA_COMMIT();
    };

    // fragment address components
    const int aRow = wm * 64 + (lane & 15);
    const uint32_t cbA  = (uint32_t)((lane >> 4) * 16);
    const uint32_t xorA = (uint32_t)((lane & 7) * 16);
    const int bRow = wn * 32 + (lane & 7) + ((lane >> 4) << 3);
    const uint32_t cbB  = (uint32_t)(((lane >> 3) & 1) * 16);
    const uint32_t xorB = (uint32_t)((lane & 7) * 16);

    float acc[4][4][4];
    #pragma unroll
    for (int i = 0; i < 4; i++)
        #pragma unroll
        for (int j = 0; j < 4; j++)
            #pragma unroll
            for (int k = 0; k < 4; k++) acc[i][j][k] = 0.f;

    uint32_t af[2][4][4], bfr[2][2][4];

    auto load_frags = [&](int buf, uint32_t sA, uint32_t sB, int kk) {
        #pragma unroll
        for (int mt = 0; mt < 4; mt++)
            ldsm4(af[buf][mt][0], af[buf][mt][1], af[buf][mt][2], af[buf][mt][3],
                  sA + (uint32_t)(aRow + mt * 16) * 128 + (((uint32_t)(32 * kk) + cbA) ^ xorA));
        #pragma unroll
        for (int nt2 = 0; nt2 < 2; nt2++)
            ldsm4(bfr[buf][nt2][0], bfr[buf][nt2][1], bfr[buf][nt2][2], bfr[buf][nt2][3],
                  sB + (uint32_t)(bRow + nt2 * 16) * 128 + (((uint32_t)(32 * kk) + cbB) ^ xorB));
    };
    auto do_mma = [&](int buf) {
        #pragma unroll
        for (int mt = 0; mt < 4; mt++)
            #pragma unroll
            for (int nt2 = 0; nt2 < 2; nt2++) {
                mma16816(acc[mt][nt2 * 2],
                         af[buf][mt][0], af[buf][mt][1], af[buf][mt][2], af[buf][mt][3],
                         bfr[buf][nt2][0], bfr[buf][nt2][1]);
                mma16816(acc[mt][nt2 * 2 + 1],
                         af[buf][mt][0], af[buf][mt][1], af[buf][mt][2], af[buf][mt][3],
                         bfr[buf][nt2][2], bfr[buf][nt2][3]);
            }
    };

    load_stage(0, 0); load_stage(1, 1); load_stage(2, 2);

    #pragma unroll 1
    for (int ks = 0; ks < NK; ks++) {
        int slot = ks & 3;
        int wg = NK - 1 - ks;
        if (wg >= 2)      asm volatile("cp.async.wait_group 2;" ::: "memory");
        else if (wg == 1) asm volatile("cp.async.wait_group 1;" ::: "memory");
        else              asm volatile("cp.async.wait_group 0;" ::: "memory");
        __syncthreads();
        if (ks + 3 < NK) load_stage((ks + 3) & 3, ks + 3);

        uint32_t sA = sm0 + slot * 32768;
        uint32_t sB = sA + 16384;
        load_frags(0, sA, sB, 0);
        #pragma unroll
        for (int kk = 0; kk < 4; kk++) {
            if (kk < 3) load_frags((kk + 1) & 1, sA, sB, kk + 1);
            do_mma(kk & 1);
        }
    }

    // -------- epilogue: direct stores from accumulator fragments ------------
    const int mBase = bm + wm * 64;
    const int nBase = bn + wn * 32;
    #pragma unroll
    for (int mt = 0; mt < 4; mt++) {
        #pragma unroll
        for (int nt = 0; nt < 4; nt++) {
            #pragma unroll
            for (int rs = 0; rs < 2; rs++) {
                int gm = mBase + mt * 16 + (lane >> 2) + rs * 8;
                int n  = nBase + nt * 8 + 2 * (lane & 3);
                float v0 = acc[mt][nt][rs * 2 + 0];
                float v1 = acc[mt][nt][rs * 2 + 1];
                if (HID) {
                    float2 bb = *(const float2*)(bias + n);
                    float h0 = fmaxf(v0 + bb.x, 0.f), h1 = fmaxf(v1 + bb.y, 0.f);
                    __nv_bfloat16 H0 = __float2bfloat16_rn(h0);
                    __nv_bfloat16 H1 = __float2bfloat16_rn(h1);
                    __nv_bfloat16 L0 = __float2bfloat16_rn(h0 - __bfloat162float(H0));
                    __nv_bfloat16 L1 = __float2bfloat16_rn(h1 - __bfloat162float(H1));
                    __nv_bfloat162 Hh, Ll; Hh.x = H0; Hh.y = H1; Ll.x = L0; Ll.y = L1;
                    __nv_bfloat16* ob = (__nv_bfloat16*)outp + (size_t)gm * K2 + n;
                    *(__nv_bfloat162*)(ob)          = Hh;
                    *(__nv_bfloat162*)(ob + NH)     = Ll;
                    *(__nv_bfloat162*)(ob + 2 * NH) = Hh;
                } else if (n < Nrows) {
                    float2 bb = *(const float2*)(bias + n);
                    *(float2*)((float*)outp + (size_t)gm * NC + n) =
                        make_float2(v0 + bb.x, v1 + bb.y);
                }
            }
        }
    }
}

// ------- 6. scalar head (hidden reconstructed from hcat hi+lo) --------------
__global__ void k_scalar(const float* __restrict__ Ws,
                         const float* __restrict__ bs,
                         const float* __restrict__ tgt) {
    int b = blockIdx.x, tid = threadIdx.x;
    const __nv_bfloat16* hrow = g_hcat + (size_t)b * K2;
    float a = 0.f;
    for (int h = tid; h < NH; h += 256) {
        float hv = __bfloat162float(hrow[h]) + __bfloat162float(hrow[NH + h]);
        a += hv * Ws[h];
    }
    __shared__ float s[256];
    s[tid] = a; __syncthreads();
    for (int off = 128; off > 0; off >>= 1) {
        if (tid < off) s[tid] += s[tid + off];
        __syncthreads();
    }
    if (tid == 0) {
        float d = s[0] + bs[0] - tgt[b];
        g_rowsq[b] = d * d;
    }
}

// ------- 7. per-row log-softmax CE + argmax ---------------------------------
__global__ void k_softmax(const int* __restrict__ tgt) {
    int b = blockIdx.x, tid = threadIdx.x;
    const float* row = g_logits + (size_t)b * NC;
    float vmax = -INFINITY; int vidx = 0x7fffffff;
    for (int c = tid; c < NC; c += 256) {
        float v = row[c];
        if (v > vmax) { vmax = v; vidx = c; }
    }
    for (int o = 16; o; o >>= 1) {
        float ov = __shfl_down_sync(0xffffffffu, vmax, o);
        int   oi = __shfl_down_sync(0xffffffffu, vidx, o);
        if (ov > vmax || (ov == vmax && oi < vidx)) { vmax = ov; vidx = oi; }
    }
    __shared__ float sv[8]; __shared__ int si[8];
    if ((tid & 31) == 0) { sv[tid >> 5] = vmax; si[tid >> 5] = vidx; }
    __syncthreads();
    __shared__ float bmax_s; __shared__ int bidx_s;
    if (tid == 0) {
        float m = sv[0]; int ix = si[0];
        for (int w = 1; w < 8; w++)
            if (sv[w] > m || (sv[w] == m && si[w] < ix)) { m = sv[w]; ix = si[w]; }
        bmax_s = m; bidx_s = ix;
    }
    __syncthreads();
    float bmax = bmax_s;
    float se = 0.f;
    for (int c = tid; c < NC; c += 256) se += expf(row[c] - bmax);
    for (int o = 16; o; o >>= 1) se += __shfl_down_sync(0xffffffffu, se, o);
    __shared__ float ss[8];
    if ((tid & 31) == 0) ss[tid >> 5] = se;
    __syncthreads();
    if (tid == 0) {
        float tot = 0.f;
        for (int w = 0; w < 8; w++) tot += ss[w];
        int t = tgt[b];
        g_rowloss[b] = -(row[t] - bmax - logf(tot));
        g_rowcorrect[b] = (bidx_s == t) ? 1.0f : 0.0f;
    }
}

// ------- 8. final reduce ----------------------------------------------------
__global__ void k_final(float* __restrict__ out) {
    int tid = threadIdx.x;
    float l = 0.f, c = 0.f, q = 0.f;
    for (int i = tid; i < NB; i += 1024) {
        l += g_rowloss[i]; c += g_rowcorrect[i]; q += g_rowsq[i];
    }
    __shared__ float sl[1024], sc[1024], sq[1024];
    sl[tid] = l; sc[tid] = c; sq[tid] = q;
    __syncthreads();
    for (int off = 512; off > 0; off >>= 1) {
        if (tid < off) {
            sl[tid] += sl[tid + off];
            sc[tid] += sc[tid + off];
            sq[tid] += sq[tid + off];
        }
        __syncthreads();
    }
    if (tid == 0) {
        float lv = sl[0] / (float)NB;
        float ls = sq[0] / (float)NB;
        out[0] = lv + ls;
        out[1] = lv;
        out[2] = ls;
        out[3] = sc[0] / (float)NB;
    }
}

// ---------------- launch ----------------------------------------------------
extern "C" void kernel_launch(void* const* d_in, const int* in_sizes, int n_in,
                              void* d_out, int out_size) {
    const float* feature = (const float*)d_in[0];
    const float* var_flat = (const float*)d_in[1];
    const int*   seg      = (const int*)d_in[2];
    const int*   tgt_vec  = (const int*)d_in[3];
    const float* tgt_sca  = (const float*)d_in[4];
    const float* Wv = (const float*)d_in[5];
    const float* bv = (const float*)d_in[6];
    const float* W1 = (const float*)d_in[7];
    const float* b1 = (const float*)d_in[8];
    const float* W2 = (const float*)d_in[9];
    const float* b2 = (const float*)d_in[10];
    const float* Ws = (const float*)d_in[11];
    const float* bs = (const float*)d_in[12];
    float* out = (float*)d_out;
    int T = in_sizes[1] / NF;

    __nv_bfloat16 *acat1_p, *w1cat_p, *hcat_p, *w2cat_p;
    float* logits_p;
    cudaGetSymbolAddress((void**)&acat1_p, g_acat1);
    cudaGetSymbolAddress((void**)&w1cat_p, g_w1cat);
    cudaGetSymbolAddress((void**)&hcat_p, g_hcat);
    cudaGetSymbolAddress((void**)&w2cat_p, g_w2cat);
    cudaGetSymbolAddress((void**)&logits_p, g_logits);

    const int SMEMG = 4 * 32768 + 1024;    // 4-stage ring + align slack
    cudaFuncSetAttribute(k_gemm_mma<true>,
                         cudaFuncAttributeMaxDynamicSharedMemorySize, SMEMG);
    cudaFuncSetAttribute(k_gemm_mma<false>,
                         cudaFuncAttributeMaxDynamicSharedMemorySize, SMEMG);

    k_starts<<<(NB + 1 + 255) / 256, 256>>>(seg, T);
    k_means<<<NB, 256>>>(var_flat);
    k_cvt_w<<<(NH * (ND / 2) + 255) / 256, 256>>>(W1, w1cat_p, NH, ND);
    k_cvt_w<<<(NC * (NH / 2) + 255) / 256, 256>>>(W2, w2cat_p, NC, NH);
    {
        dim3 g(ND / 64, NB / 128);
        k_combined<<<g, 256>>>(feature, Wv, bv);
    }
    {   // hidden = relu(combined @ W1^T + b1) -> hcat (A-pattern)
        dim3 g(NH / 128, NB / 128);
        k_gemm_mma<true><<<g, 256, SMEMG>>>(acat1_p, w1cat_p, b1, hcat_p,
                                            K1, NH, K1 / 64);
    }
    {   // logits = hidden @ W2^T + b2
        dim3 g(1024 / 128, NB / 128);
        k_gemm_mma<false><<<g, 256, SMEMG>>>(hcat_p, w2cat_p, b2, logits_p,
                                             K2, NC, K2 / 64);
    }
    k_scalar<<<NB, 256>>>(Ws, bs, tgt_sca);
    k_softmax<<<NB, 256>>>(tgt_vec);
    k_final<<<1, 1024>>>(out);
}

// round 7
// speedup vs baseline: 2.5614x; 1.0975x over previous
#include <cuda_runtime.h>
#include <cuda_bf16.h>
#include <math.h>
#include <stdint.h>

#define NB 4096
#define ND 1024
#define NH 2048
#define NC 1000
#define NF 32
#define K1 (3*ND)   // 3072 split-cat K for GEMM1
#define K2 (3*NH)   // 6144 split-cat K for GEMM2

// ---------------- scratch ---------------------------------------------------
__device__ float g_means[NB * NF];
__device__ __align__(16) __nv_bfloat16 g_acat1[(size_t)NB * K1];
__device__ __align__(16) __nv_bfloat16 g_w1cat[(size_t)NH * K1];
__device__ __align__(16) __nv_bfloat16 g_hcat[(size_t)NB * K2];
__device__ __align__(16) __nv_bfloat16 g_w2cat[(size_t)NC * K2];
__device__ float g_logits[(size_t)NB * NC];
__device__ float g_rowloss[NB];
__device__ float g_rowcorrect[NB];
__device__ float g_rowsq[NB];
__device__ int   g_starts[NB + 1];

// ---------------- helpers ---------------------------------------------------
__device__ __forceinline__ uint32_t smem_u32(const void* p) {
    uint32_t a;
    asm("{ .reg .u64 t; cvta.to.shared.u64 t, %1; cvt.u32.u64 %0, t; }"
        : "=r"(a) : "l"(p));
    return a;
}

__device__ __forceinline__ void ldsm4(uint32_t& r0, uint32_t& r1, uint32_t& r2,
                                      uint32_t& r3, uint32_t a) {
    asm volatile("ldmatrix.sync.aligned.m8n8.x4.shared.b16 {%0,%1,%2,%3}, [%4];"
                 : "=r"(r0), "=r"(r1), "=r"(r2), "=r"(r3) : "r"(a));
}

__device__ __forceinline__ void mma16816(float* c, uint32_t a0, uint32_t a1,
                                         uint32_t a2, uint32_t a3,
                                         uint32_t b0, uint32_t b1) {
    asm volatile(
        "mma.sync.aligned.m16n8k16.row.col.f32.bf16.bf16.f32 "
        "{%0,%1,%2,%3}, {%4,%5,%6,%7}, {%8,%9}, {%0,%1,%2,%3};"
        : "+f"(c[0]), "+f"(c[1]), "+f"(c[2]), "+f"(c[3])
        : "r"(a0), "r"(a1), "r"(a2), "r"(a3), "r"(b0), "r"(b1));
}

#define CPA16(sa, ga, pbytes) \
    asm volatile("cp.async.cg.shared.global [%0], [%1], 16, %2;" \
                 :: "r"(sa), "l"(ga), "r"(pbytes))
#define CPA_COMMIT() asm volatile("cp.async.commit_group;" ::: "memory")

// ---------------- 1. segment starts -----------------------------------------
__global__ void k_starts(const int* __restrict__ seg, int T) {
    int b = blockIdx.x * blockDim.x + threadIdx.x;
    if (b > NB) return;
    int lo = 0, hi = T;
    while (lo < hi) { int m = (lo + hi) >> 1; if (seg[m] < b) lo = m + 1; else hi = m; }
    g_starts[b] = lo;
}

// ---------------- 2. per-segment mean ---------------------------------------
__global__ void k_means(const float* __restrict__ vf) {
    int b = blockIdx.x;
    int start = g_starts[b], end = g_starts[b + 1];
    int tid = threadIdx.x;
    int j = tid & 7, r = tid >> 3;
    float4 acc = make_float4(0.f, 0.f, 0.f, 0.f);
    for (int row = start + r; row < end; row += 32) {
        float4 v = *(const float4*)(vf + (size_t)row * NF + j * 4);
        acc.x += v.x; acc.y += v.y; acc.z += v.z; acc.w += v.w;
    }
    __shared__ float4 s[256];
    s[tid] = acc; __syncthreads();
    for (int off = 128; off >= 8; off >>= 1) {
        if (tid < off) {
            float4 o = s[tid + off]; float4 m = s[tid];
            m.x += o.x; m.y += o.y; m.z += o.z; m.w += o.w; s[tid] = m;
        }
        __syncthreads();
    }
    if (tid < 8) {
        float inv = 1.0f / fmaxf((float)(end - start), 1.0f);
        float4 m = s[tid];
        m.x *= inv; m.y *= inv; m.z *= inv; m.w *= inv;
        *(float4*)(g_means + (size_t)b * NF + tid * 4) = m;
    }
}

// ------- 3. weight fp32 -> bf16 3-seg B-pattern [hi, hi, lo], vectorized ----
__global__ void k_cvt_w(const float* __restrict__ W, __nv_bfloat16* __restrict__ out,
                        int R, int K) {
    int q = K >> 2;
    int idx = blockIdx.x * blockDim.x + threadIdx.x;
    if (idx >= R * q) return;
    int r = idx / q;
    int c = (idx - r * q) * 4;
    float4 v = *(const float4*)(W + (size_t)r * K + c);
    __nv_bfloat16 h0 = __float2bfloat16_rn(v.x), h1 = __float2bfloat16_rn(v.y);
    __nv_bfloat16 h2 = __float2bfloat16_rn(v.z), h3 = __float2bfloat16_rn(v.w);
    __nv_bfloat16 l0 = __float2bfloat16_rn(v.x - __bfloat162float(h0));
    __nv_bfloat16 l1 = __float2bfloat16_rn(v.y - __bfloat162float(h1));
    __nv_bfloat16 l2 = __float2bfloat16_rn(v.z - __bfloat162float(h2));
    __nv_bfloat16 l3 = __float2bfloat16_rn(v.w - __bfloat162float(h3));
    union { __nv_bfloat16 b[4]; uint2 u; } H, L;
    H.b[0] = h0; H.b[1] = h1; H.b[2] = h2; H.b[3] = h3;
    L.b[0] = l0; L.b[1] = l1; L.b[2] = l2; L.b[3] = l3;
    __nv_bfloat16* ob = out + (size_t)r * (3 * K) + c;
    *(uint2*)(ob)         = H.u;
    *(uint2*)(ob + K)     = H.u;
    *(uint2*)(ob + 2 * K) = L.u;
}

// ------- 4. combined = feature + means @ Wv^T + bv -> A-pattern [hi, lo, hi] -
__global__ void k_combined(const float* __restrict__ feat,
                           const float* __restrict__ Wv,
                           const float* __restrict__ bv) {
    __shared__ float wv_s[NF][64];
    __shared__ float me_s[NF][128];
    int d0 = blockIdx.x * 64, b0 = blockIdx.y * 128;
    int tid = threadIdx.x;
    for (int idx = tid; idx < 64 * 8; idx += 256) {
        int dd = idx >> 3, fg = (idx & 7) * 4;
        float4 v = *(const float4*)(Wv + (size_t)(d0 + dd) * NF + fg);
        wv_s[fg + 0][dd] = v.x; wv_s[fg + 1][dd] = v.y;
        wv_s[fg + 2][dd] = v.z; wv_s[fg + 3][dd] = v.w;
    }
    for (int idx = tid; idx < 128 * 8; idx += 256) {
        int bb = idx >> 3, fg = (idx & 7) * 4;
        float4 v = *(const float4*)(g_means + (size_t)(b0 + bb) * NF + fg);
        me_s[fg + 0][bb] = v.x; me_s[fg + 1][bb] = v.y;
        me_s[fg + 2][bb] = v.z; me_s[fg + 3][bb] = v.w;
    }
    __syncthreads();
    int tx = tid & 15, ty = tid >> 4;
    float acc[8][4];
    #pragma unroll
    for (int r = 0; r < 8; r++)
        #pragma unroll
        for (int c = 0; c < 4; c++) acc[r][c] = 0.f;
    #pragma unroll 4
    for (int f = 0; f < NF; f++) {
        float w[4], m[8];
        #pragma unroll
        for (int c = 0; c < 4; c++) w[c] = wv_s[f][tx * 4 + c];
        #pragma unroll
        for (int r = 0; r < 8; r++) m[r] = me_s[f][ty * 8 + r];
        #pragma unroll
        for (int r = 0; r < 8; r++)
            #pragma unroll
            for (int c = 0; c < 4; c++) acc[r][c] += m[r] * w[c];
    }
    int d = d0 + tx * 4;
    float4 bvv = *(const float4*)(bv + d);
    #pragma unroll
    for (int r = 0; r < 8; r++) {
        int b = b0 + ty * 8 + r;
        float4 fv = *(const float4*)(feat + (size_t)b * ND + d);
        float o[4] = { fv.x + bvv.x + acc[r][0], fv.y + bvv.y + acc[r][1],
                       fv.z + bvv.z + acc[r][2], fv.w + bvv.w + acc[r][3] };
        __nv_bfloat16* ob = g_acat1 + (size_t)b * K1 + d;
        #pragma unroll
        for (int p = 0; p < 2; p++) {
            __nv_bfloat16 h0 = __float2bfloat16_rn(o[p * 2]);
            __nv_bfloat16 h1 = __float2bfloat16_rn(o[p * 2 + 1]);
            __nv_bfloat16 l0 = __float2bfloat16_rn(o[p * 2] - __bfloat162float(h0));
            __nv_bfloat16 l1 = __float2bfloat16_rn(o[p * 2 + 1] - __bfloat162float(h1));
            __nv_bfloat162 H, L; H.x = h0; H.y = h1; L.x = l0; L.y = l1;
            *(__nv_bfloat162*)(ob + p * 2)          = H;
            *(__nv_bfloat162*)(ob + ND + p * 2)     = L;
            *(__nv_bfloat162*)(ob + 2 * ND + p * 2) = H;
        }
    }
}

// ------- 5. mma.sync GEMM: C = A @ B^T (+bias; relu+split or fp32 store) ----
// 128x128x64 tiles, 3-stage cp.async ring, 2 CTAs/SM, single-buffer frags.
template <bool HID>
__global__ void __launch_bounds__(256, 2)
k_gemm_mma(const __nv_bfloat16* __restrict__ A, const __nv_bfloat16* __restrict__ B,
           const float* __restrict__ bias, void* __restrict__ outp,
           int Kp, int Nrows, int NK) {
    extern __shared__ char dsm[];
    uint32_t raw = smem_u32(dsm);
    const uint32_t sm0 = (raw + 1023u) & ~1023u;

    const int tid = threadIdx.x, wid = tid >> 5, lane = tid & 31;
    const int wm = wid & 1, wn = wid >> 1;
    const int bm = blockIdx.y * 128, bn = blockIdx.x * 128;
    const size_t rowb = (size_t)Kp * 2;

    const int lrow0 = tid >> 3;
    const int ls    = tid & 7;
    const uint32_t lsw = (uint32_t)((ls * 16) ^ ((lrow0 & 7) * 16));

    auto load_stage = [&](int slot, int kt) {
        uint32_t sb = sm0 + slot * 32768;
        int k0b = kt * 128;
        #pragma unroll
        for (int i = 0; i < 4; i++) {
            int r = lrow0 + i * 32;
            uint32_t sa = sb + r * 128 + lsw;
            const char* g = (const char*)A + (size_t)(bm + r) * rowb + k0b + ls * 16;
            CPA16(sa, g, 16);
        }
        #pragma unroll
        for (int i = 0; i < 4; i++) {
            int r = lrow0 + i * 32;
            int gr = bn + r;
            bool v = gr < Nrows;
            uint32_t sa = sb + 16384 + r * 128 + lsw;
            const char* g = (const char*)B + (size_t)(v ? gr : 0) * rowb + k0b + ls * 16;
            CPA16(sa, g, v ? 16 : 0);
        }
        CPA_COMMIT();
    };

    const int aRow = wm * 64 + (lane & 15);
    const uint32_t cbA  = (uint32_t)((lane >> 4) * 16);
    const uint32_t xorA = (uint32_t)((lane & 7) * 16);
    const int bRow = wn * 32 + (lane & 7) + ((lane >> 4) << 3);
    const uint32_t cbB  = (uint32_t)(((lane >> 3) & 1) * 16);
    const uint32_t xorB = (uint32_t)((lane & 7) * 16);

    float acc[4][4][4];
    #pragma unroll
    for (int i = 0; i < 4; i++)
        #pragma unroll
        for (int j = 0; j < 4; j++)
            #pragma unroll
            for (int k = 0; k < 4; k++) acc[i][j][k] = 0.f;

    uint32_t af[4][4], bfr[2][4];

    load_stage(0, 0); load_stage(1, 1);

    #pragma unroll 1
    for (int ks = 0; ks < NK; ks++) {
        int slot = ks - (ks / 3) * 3;
        asm volatile("cp.async.wait_group 1;" ::: "memory");
        __syncthreads();
        if (ks + 2 < NK) {
            int s2 = (ks + 2) - ((ks + 2) / 3) * 3;
            load_stage(s2, ks + 2);
        }
        uint32_t sA = sm0 + slot * 32768;
        uint32_t sB = sA + 16384;
        #pragma unroll
        for (int kk = 0; kk < 4; kk++) {
            #pragma unroll
            for (int mt = 0; mt < 4; mt++)
                ldsm4(af[mt][0], af[mt][1], af[mt][2], af[mt][3],
                      sA + (uint32_t)(aRow + mt * 16) * 128 +
                          (((uint32_t)(32 * kk) + cbA) ^ xorA));
            #pragma unroll
            for (int nt2 = 0; nt2 < 2; nt2++)
                ldsm4(bfr[nt2][0], bfr[nt2][1], bfr[nt2][2], bfr[nt2][3],
                      sB + (uint32_t)(bRow + nt2 * 16) * 128 +
                          (((uint32_t)(32 * kk) + cbB) ^ xorB));
            #pragma unroll
            for (int mt = 0; mt < 4; mt++)
                #pragma unroll
                for (int nt2 = 0; nt2 < 2; nt2++) {
                    mma16816(acc[mt][nt2 * 2],
                             af[mt][0], af[mt][1], af[mt][2], af[mt][3],
                             bfr[nt2][0], bfr[nt2][1]);
                    mma16816(acc[mt][nt2 * 2 + 1],
                             af[mt][0], af[mt][1], af[mt][2], af[mt][3],
                             bfr[nt2][2], bfr[nt2][3]);
                }
        }
    }

    // -------- epilogue: direct stores from accumulator fragments ------------
    const int mBase = bm + wm * 64;
    const int nBase = bn + wn * 32;
    #pragma unroll
    for (int mt = 0; mt < 4; mt++) {
        #pragma unroll
        for (int nt = 0; nt < 4; nt++) {
            #pragma unroll
            for (int rs = 0; rs < 2; rs++) {
                int gm = mBase + mt * 16 + (lane >> 2) + rs * 8;
                int n  = nBase + nt * 8 + 2 * (lane & 3);
                float v0 = acc[mt][nt][rs * 2 + 0];
                float v1 = acc[mt][nt][rs * 2 + 1];
                if (HID) {
                    float2 bb = *(const float2*)(bias + n);
                    float h0 = fmaxf(v0 + bb.x, 0.f), h1 = fmaxf(v1 + bb.y, 0.f);
                    __nv_bfloat16 H0 = __float2bfloat16_rn(h0);
                    __nv_bfloat16 H1 = __float2bfloat16_rn(h1);
                    __nv_bfloat16 L0 = __float2bfloat16_rn(h0 - __bfloat162float(H0));
                    __nv_bfloat16 L1 = __float2bfloat16_rn(h1 - __bfloat162float(H1));
                    __nv_bfloat162 Hh, Ll; Hh.x = H0; Hh.y = H1; Ll.x = L0; Ll.y = L1;
                    __nv_bfloat16* ob = (__nv_bfloat16*)outp + (size_t)gm * K2 + n;
                    *(__nv_bfloat162*)(ob)          = Hh;
                    *(__nv_bfloat162*)(ob + NH)     = Ll;
                    *(__nv_bfloat162*)(ob + 2 * NH) = Hh;
                } else if (n < Nrows) {
                    float2 bb = *(const float2*)(bias + n);
                    *(float2*)((float*)outp + (size_t)gm * NC + n) =
                        make_float2(v0 + bb.x, v1 + bb.y);
                }
            }
        }
    }
}

// ------- 6. scalar head (hidden reconstructed from hcat hi+lo) --------------
__global__ void k_scalar(const float* __restrict__ Ws,
                         const float* __restrict__ bs,
                         const float* __restrict__ tgt) {
    int b = blockIdx.x, tid = threadIdx.x;
    const __nv_bfloat16* hrow = g_hcat + (size_t)b * K2;
    float a = 0.f;
    for (int h = tid; h < NH; h += 256) {
        float hv = __bfloat162float(hrow[h]) + __bfloat162float(hrow[NH + h]);
        a += hv * Ws[h];
    }
    __shared__ float s[256];
    s[tid] = a; __syncthreads();
    for (int off = 128; off > 0; off >>= 1) {
        if (tid < off) s[tid] += s[tid + off];
        __syncthreads();
    }
    if (tid == 0) {
        float d = s[0] + bs[0] - tgt[b];
        g_rowsq[b] = d * d;
    }
}

// ------- 7. per-row log-softmax CE + argmax ---------------------------------
__global__ void k_softmax(const int* __restrict__ tgt) {
    int b = blockIdx.x, tid = threadIdx.x;
    const float* row = g_logits + (size_t)b * NC;
    float vmax = -INFINITY; int vidx = 0x7fffffff;
    for (int c = tid; c < NC; c += 256) {
        float v = row[c];
        if (v > vmax) { vmax = v; vidx = c; }
    }
    for (int o = 16; o; o >>= 1) {
        float ov = __shfl_down_sync(0xffffffffu, vmax, o);
        int   oi = __shfl_down_sync(0xffffffffu, vidx, o);
        if (ov > vmax || (ov == vmax && oi < vidx)) { vmax = ov; vidx = oi; }
    }
    __shared__ float sv[8]; __shared__ int si[8];
    if ((tid & 31) == 0) { sv[tid >> 5] = vmax; si[tid >> 5] = vidx; }
    __syncthreads();
    __shared__ float bmax_s; __shared__ int bidx_s;
    if (tid == 0) {
        float m = sv[0]; int ix = si[0];
        for (int w = 1; w < 8; w++)
            if (sv[w] > m || (sv[w] == m && si[w] < ix)) { m = sv[w]; ix = si[w]; }
        bmax_s = m; bidx_s = ix;
    }
    __syncthreads();
    float bmax = bmax_s;
    float se = 0.f;
    for (int c = tid; c < NC; c += 256) se += expf(row[c] - bmax);
    for (int o = 16; o; o >>= 1) se += __shfl_down_sync(0xffffffffu, se, o);
    __shared__ float ss[8];
    if ((tid & 31) == 0) ss[tid >> 5] = se;
    __syncthreads();
    if (tid == 0) {
        float tot = 0.f;
        for (int w = 0; w < 8; w++) tot += ss[w];
        int t = tgt[b];
        g_rowloss[b] = -(row[t] - bmax - logf(tot));
        g_rowcorrect[b] = (bidx_s == t) ? 1.0f : 0.0f;
    }
}

// ------- 8. final reduce ----------------------------------------------------
__global__ void k_final(float* __restrict__ out) {
    int tid = threadIdx.x;
    float l = 0.f, c = 0.f, q = 0.f;
    for (int i = tid; i < NB; i += 1024) {
        l += g_rowloss[i]; c += g_rowcorrect[i]; q += g_rowsq[i];
    }
    __shared__ float sl[1024], sc[1024], sq[1024];
    sl[tid] = l; sc[tid] = c; sq[tid] = q;
    __syncthreads();
    for (int off = 512; off > 0; off >>= 1) {
        if (tid < off) {
            sl[tid] += sl[tid + off];
            sc[tid] += sc[tid + off];
            sq[tid] += sq[tid + off];
        }
        __syncthreads();
    }
    if (tid == 0) {
        float lv = sl[0] / (float)NB;
        float ls = sq[0] / (float)NB;
        out[0] = lv + ls;
        out[1] = lv;
        out[2] = ls;
        out[3] = sc[0] / (float)NB;
    }
}

// ---------------- launch ----------------------------------------------------
extern "C" void kernel_launch(void* const* d_in, const int* in_sizes, int n_in,
                              void* d_out, int out_size) {
    const float* feature = (const float*)d_in[0];
    const float* var_flat = (const float*)d_in[1];
    const int*   seg      = (const int*)d_in[2];
    const int*   tgt_vec  = (const int*)d_in[3];
    const float* tgt_sca  = (const float*)d_in[4];
    const float* Wv = (const float*)d_in[5];
    const float* bv = (const float*)d_in[6];
    const float* W1 = (const float*)d_in[7];
    const float* b1 = (const float*)d_in[8];
    const float* W2 = (const float*)d_in[9];
    const float* b2 = (const float*)d_in[10];
    const float* Ws = (const float*)d_in[11];
    const float* bs = (const float*)d_in[12];
    float* out = (float*)d_out;
    int T = in_sizes[1] / NF;

    __nv_bfloat16 *acat1_p, *w1cat_p, *hcat_p, *w2cat_p;
    float* logits_p;
    cudaGetSymbolAddress((void**)&acat1_p, g_acat1);
    cudaGetSymbolAddress((void**)&w1cat_p, g_w1cat);
    cudaGetSymbolAddress((void**)&hcat_p, g_hcat);
    cudaGetSymbolAddress((void**)&w2cat_p, g_w2cat);
    cudaGetSymbolAddress((void**)&logits_p, g_logits);

    const int SMEMG = 3 * 32768 + 1024;    // 3-stage ring + align slack
    cudaFuncSetAttribute(k_gemm_mma<true>,
                         cudaFuncAttributeMaxDynamicSharedMemorySize, SMEMG);
    cudaFuncSetAttribute(k_gemm_mma<false>,
                         cudaFuncAttributeMaxDynamicSharedMemorySize, SMEMG);

    k_starts<<<(NB + 1 + 255) / 256, 256>>>(seg, T);
    k_means<<<NB, 256>>>(var_flat);
    k_cvt_w<<<(NH * (ND / 4) + 255) / 256, 256>>>(W1, w1cat_p, NH, ND);
    k_cvt_w<<<(NC * (NH / 4) + 255) / 256, 256>>>(W2, w2cat_p, NC, NH);
    {
        dim3 g(ND / 64, NB / 128);
        k_combined<<<g, 256>>>(feature, Wv, bv);
    }
    {   // hidden = relu(combined @ W1^T + b1) -> hcat (A-pattern)
        dim3 g(NH / 128, NB / 128);
        k_gemm_mma<true><<<g, 256, SMEMG>>>(acat1_p, w1cat_p, b1, hcat_p,
                                            K1, NH, K1 / 64);
    }
    {   // logits = hidden @ W2^T + b2
        dim3 g(1024 / 128, NB / 128);
        k_gemm_mma<false><<<g, 256, SMEMG>>>(hcat_p, w2cat_p, b2, logits_p,
                                             K2, NC, K2 / 64);
    }
    k_scalar<<<NB, 256>>>(Ws, bs, tgt_sca);
    k_softmax<<<NB, 256>>>(tgt_vec);
    k_final<<<1, 1024>>>(out);
}

// round 9
// speedup vs baseline: 2.5794x; 1.0070x over previous
#include <cuda_runtime.h>
#include <cuda_bf16.h>
#include <math.h>
#include <stdint.h>

#define NB 4096
#define ND 1024
#define NH 2048
#define NC 1000
#define NF 32
#define K1 (3*ND)   // 3072 split-cat K for GEMM1
#define K2 (3*NH)   // 6144 split-cat K for GEMM2

// ---------------- scratch ---------------------------------------------------
__device__ float g_means[NB * NF];
__device__ __align__(16) __nv_bfloat16 g_acat1[(size_t)NB * K1];
__device__ __align__(16) __nv_bfloat16 g_w1cat[(size_t)NH * K1];
__device__ __align__(16) __nv_bfloat16 g_hcat[(size_t)NB * K2];
__device__ __align__(16) __nv_bfloat16 g_w2cat[(size_t)NC * K2];
__device__ float g_logits[(size_t)NB * NC];
__device__ float g_rowloss[NB];
__device__ float g_rowcorrect[NB];
__device__ float g_rowsq[NB];
__device__ int   g_starts[NB + 1];

// ---------------- helpers ---------------------------------------------------
__device__ __forceinline__ uint32_t smem_u32(const void* p) {
    uint32_t a;
    asm("{ .reg .u64 t; cvta.to.shared.u64 t, %1; cvt.u32.u64 %0, t; }"
        : "=r"(a) : "l"(p));
    return a;
}

__device__ __forceinline__ void ldsm4(uint32_t& r0, uint32_t& r1, uint32_t& r2,
                                      uint32_t& r3, uint32_t a) {
    asm volatile("ldmatrix.sync.aligned.m8n8.x4.shared.b16 {%0,%1,%2,%3}, [%4];"
                 : "=r"(r0), "=r"(r1), "=r"(r2), "=r"(r3) : "r"(a));
}

__device__ __forceinline__ void mma16816(float* c, uint32_t a0, uint32_t a1,
                                         uint32_t a2, uint32_t a3,
                                         uint32_t b0, uint32_t b1) {
    asm volatile(
        "mma.sync.aligned.m16n8k16.row.col.f32.bf16.bf16.f32 "
        "{%0,%1,%2,%3}, {%4,%5,%6,%7}, {%8,%9}, {%0,%1,%2,%3};"
        : "+f"(c[0]), "+f"(c[1]), "+f"(c[2]), "+f"(c[3])
        : "r"(a0), "r"(a1), "r"(a2), "r"(a3), "r"(b0), "r"(b1));
}

#define CPA16(sa, ga, pbytes) \
    asm volatile("cp.async.cg.shared.global [%0], [%1], 16, %2;" \
                 :: "r"(sa), "l"(ga), "r"(pbytes))
#define CPA_COMMIT() asm volatile("cp.async.commit_group;" ::: "memory")

// ---------------- 1. segment starts -----------------------------------------
__global__ void k_starts(const int* __restrict__ seg, int T) {
    int b = blockIdx.x * blockDim.x + threadIdx.x;
    if (b > NB) return;
    int lo = 0, hi = T;
    while (lo < hi) { int m = (lo + hi) >> 1; if (seg[m] < b) lo = m + 1; else hi = m; }
    g_starts[b] = lo;
}

// ---------------- 2. per-segment mean ---------------------------------------
__global__ void k_means(const float* __restrict__ vf) {
    int b = blockIdx.x;
    int start = g_starts[b], end = g_starts[b + 1];
    int tid = threadIdx.x;
    int j = tid & 7, r = tid >> 3;
    float4 acc = make_float4(0.f, 0.f, 0.f, 0.f);
    for (int row = start + r; row < end; row += 32) {
        float4 v = *(const float4*)(vf + (size_t)row * NF + j * 4);
        acc.x += v.x; acc.y += v.y; acc.z += v.z; acc.w += v.w;
    }
    __shared__ float4 s[256];
    s[tid] = acc; __syncthreads();
    for (int off = 128; off >= 8; off >>= 1) {
        if (tid < off) {
            float4 o = s[tid + off]; float4 m = s[tid];
            m.x += o.x; m.y += o.y; m.z += o.z; m.w += o.w; s[tid] = m;
        }
        __syncthreads();
    }
    if (tid < 8) {
        float inv = 1.0f / fmaxf((float)(end - start), 1.0f);
        float4 m = s[tid];
        m.x *= inv; m.y *= inv; m.z *= inv; m.w *= inv;
        *(float4*)(g_means + (size_t)b * NF + tid * 4) = m;
    }
}

// ------- 3. weight fp32 -> bf16 3-seg B-pattern [hi, hi, lo], vectorized ----
__global__ void k_cvt_w(const float* __restrict__ W, __nv_bfloat16* __restrict__ out,
                        int R, int K) {
    int q = K >> 2;
    int idx = blockIdx.x * blockDim.x + threadIdx.x;
    if (idx >= R * q) return;
    int r = idx / q;
    int c = (idx - r * q) * 4;
    float4 v = *(const float4*)(W + (size_t)r * K + c);
    __nv_bfloat16 h0 = __float2bfloat16_rn(v.x), h1 = __float2bfloat16_rn(v.y);
    __nv_bfloat16 h2 = __float2bfloat16_rn(v.z), h3 = __float2bfloat16_rn(v.w);
    __nv_bfloat16 l0 = __float2bfloat16_rn(v.x - __bfloat162float(h0));
    __nv_bfloat16 l1 = __float2bfloat16_rn(v.y - __bfloat162float(h1));
    __nv_bfloat16 l2 = __float2bfloat16_rn(v.z - __bfloat162float(h2));
    __nv_bfloat16 l3 = __float2bfloat16_rn(v.w - __bfloat162float(h3));
    union { __nv_bfloat16 b[4]; uint2 u; } H, L;
    H.b[0] = h0; H.b[1] = h1; H.b[2] = h2; H.b[3] = h3;
    L.b[0] = l0; L.b[1] = l1; L.b[2] = l2; L.b[3] = l3;
    __nv_bfloat16* ob = out + (size_t)r * (3 * K) + c;
    *(uint2*)(ob)         = H.u;
    *(uint2*)(ob + K)     = H.u;
    *(uint2*)(ob + 2 * K) = L.u;
}

// ------- 4. combined = feature + means @ Wv^T + bv -> A-pattern [hi, lo, hi] -
__global__ void k_combined(const float* __restrict__ feat,
                           const float* __restrict__ Wv,
                           const float* __restrict__ bv) {
    __shared__ float wv_s[NF][64];
    __shared__ float me_s[NF][128];
    int d0 = blockIdx.x * 64, b0 = blockIdx.y * 128;
    int tid = threadIdx.x;
    for (int idx = tid; idx < 64 * 8; idx += 256) {
        int dd = idx >> 3, fg = (idx & 7) * 4;
        float4 v = *(const float4*)(Wv + (size_t)(d0 + dd) * NF + fg);
        wv_s[fg + 0][dd] = v.x; wv_s[fg + 1][dd] = v.y;
        wv_s[fg + 2][dd] = v.z; wv_s[fg + 3][dd] = v.w;
    }
    for (int idx = tid; idx < 128 * 8; idx += 256) {
        int bb = idx >> 3, fg = (idx & 7) * 4;
        float4 v = *(const float4*)(g_means + (size_t)(b0 + bb) * NF + fg);
        me_s[fg + 0][bb] = v.x; me_s[fg + 1][bb] = v.y;
        me_s[fg + 2][bb] = v.z; me_s[fg + 3][bb] = v.w;
    }
    __syncthreads();
    int tx = tid & 15, ty = tid >> 4;
    float acc[8][4];
    #pragma unroll
    for (int r = 0; r < 8; r++)
        #pragma unroll
        for (int c = 0; c < 4; c++) acc[r][c] = 0.f;
    #pragma unroll 4
    for (int f = 0; f < NF; f++) {
        float w[4], m[8];
        #pragma unroll
        for (int c = 0; c < 4; c++) w[c] = wv_s[f][tx * 4 + c];
        #pragma unroll
        for (int r = 0; r < 8; r++) m[r] = me_s[f][ty * 8 + r];
        #pragma unroll
        for (int r = 0; r < 8; r++)
            #pragma unroll
            for (int c = 0; c < 4; c++) acc[r][c] += m[r] * w[c];
    }
    int d = d0 + tx * 4;
    float4 bvv = *(const float4*)(bv + d);
    #pragma unroll
    for (int r = 0; r < 8; r++) {
        int b = b0 + ty * 8 + r;
        float4 fv = *(const float4*)(feat + (size_t)b * ND + d);
        float o[4] = { fv.x + bvv.x + acc[r][0], fv.y + bvv.y + acc[r][1],
                       fv.z + bvv.z + acc[r][2], fv.w + bvv.w + acc[r][3] };
        __nv_bfloat16* ob = g_acat1 + (size_t)b * K1 + d;
        #pragma unroll
        for (int p = 0; p < 2; p++) {
            __nv_bfloat16 h0 = __float2bfloat16_rn(o[p * 2]);
            __nv_bfloat16 h1 = __float2bfloat16_rn(o[p * 2 + 1]);
            __nv_bfloat16 l0 = __float2bfloat16_rn(o[p * 2] - __bfloat162float(h0));
            __nv_bfloat16 l1 = __float2bfloat16_rn(o[p * 2 + 1] - __bfloat162float(h1));
            __nv_bfloat162 H, L; H.x = h0; H.y = h1; L.x = l0; L.y = l1;
            *(__nv_bfloat162*)(ob + p * 2)          = H;
            *(__nv_bfloat162*)(ob + ND + p * 2)     = L;
            *(__nv_bfloat162*)(ob + 2 * ND + p * 2) = H;
        }
    }
}

// ------- 5. mma.sync GEMM: C = A @ B^T (+bias; relu+split or fp32 store) ----
// 128x128x64 tiles, 3-stage cp.async ring, 2 CTAs/SM, double-buffered frags.
template <bool HID>
__global__ void __launch_bounds__(256, 2)
k_gemm_mma(const __nv_bfloat16* __restrict__ A, const __nv_bfloat16* __restrict__ B,
           const float* __restrict__ bias, void* __restrict__ outp,
           int Kp, int Nrows, int NK) {
    extern __shared__ char dsm[];
    uint32_t raw = smem_u32(dsm);
    const uint32_t sm0 = (raw + 1023u) & ~1023u;

    const int tid = threadIdx.x, wid = tid >> 5, lane = tid & 31;
    const int wm = wid & 1, wn = wid >> 1;
    const int bm = blockIdx.y * 128, bn = blockIdx.x * 128;
    const size_t rowb = (size_t)Kp * 2;

    const int lrow0 = tid >> 3;
    const int ls    = tid & 7;
    const uint32_t lsw = (uint32_t)((ls * 16) ^ ((lrow0 & 7) * 16));

    auto load_stage = [&](int slot, int kt) {
        uint32_t sb = sm0 + slot * 32768;
        int k0b = kt * 128;
        #pragma unroll
        for (int i = 0; i < 4; i++) {
            int r = lrow0 + i * 32;
            uint32_t sa = sb + r * 128 + lsw;
            const char* g = (const char*)A + (size_t)(bm + r) * rowb + k0b + ls * 16;
            CPA16(sa, g, 16);
        }
        #pragma unroll
        for (int i = 0; i < 4; i++) {
            int r = lrow0 + i * 32;
            int gr = bn + r;
            bool v = gr < Nrows;
            uint32_t sa = sb + 16384 + r * 128 + lsw;
            const char* g = (const char*)B + (size_t)(v ? gr : 0) * rowb + k0b + ls * 16;
            CPA16(sa, g, v ? 16 : 0);
        }
        CPA_COMMIT();
    };

    const int aRow = wm * 64 + (lane & 15);
    const uint32_t cbA  = (uint32_t)((lane >> 4) * 16);
    const uint32_t xorA = (uint32_t)((lane & 7) * 16);
    const int bRow = wn * 32 + (lane & 7) + ((lane >> 4) << 3);
    const uint32_t cbB  = (uint32_t)(((lane >> 3) & 1) * 16);
    const uint32_t xorB = (uint32_t)((lane & 7) * 16);

    float acc[4][4][4];
    #pragma unroll
    for (int i = 0; i < 4; i++)
        #pragma unroll
        for (int j = 0; j < 4; j++)
            #pragma unroll
            for (int k = 0; k < 4; k++) acc[i][j][k] = 0.f;

    uint32_t af[2][4][4], bfr[2][2][4];

    auto load_frags = [&](int buf, uint32_t sA, uint32_t sB, int kk) {
        #pragma unroll
        for (int mt = 0; mt < 4; mt++)
            ldsm4(af[buf][mt][0], af[buf][mt][1], af[buf][mt][2], af[buf][mt][3],
                  sA + (uint32_t)(aRow + mt * 16) * 128 +
                      (((uint32_t)(32 * kk) + cbA) ^ xorA));
        #pragma unroll
        for (int nt2 = 0; nt2 < 2; nt2++)
            ldsm4(bfr[buf][nt2][0], bfr[buf][nt2][1], bfr[buf][nt2][2], bfr[buf][nt2][3],
                  sB + (uint32_t)(bRow + nt2 * 16) * 128 +
                      (((uint32_t)(32 * kk) + cbB) ^ xorB));
    };
    auto do_mma = [&](int buf) {
        #pragma unroll
        for (int mt = 0; mt < 4; mt++)
            #pragma unroll
            for (int nt2 = 0; nt2 < 2; nt2++) {
                mma16816(acc[mt][nt2 * 2],
                         af[buf][mt][0], af[buf][mt][1], af[buf][mt][2], af[buf][mt][3],
                         bfr[buf][nt2][0], bfr[buf][nt2][1]);
                mma16816(acc[mt][nt2 * 2 + 1],
                         af[buf][mt][0], af[buf][mt][1], af[buf][mt][2], af[buf][mt][3],
                         bfr[buf][nt2][2], bfr[buf][nt2][3]);
            }
    };

    load_stage(0, 0); load_stage(1, 1);

    #pragma unroll 1
    for (int ks = 0; ks < NK; ks++) {
        int slot = ks - (ks / 3) * 3;
        asm volatile("cp.async.wait_group 1;" ::: "memory");
        __syncthreads();
        if (ks + 2 < NK) {
            int s2 = (ks + 2) - ((ks + 2) / 3) * 3;
            load_stage(s2, ks + 2);
        }
        uint32_t sA = sm0 + slot * 32768;
        uint32_t sB = sA + 16384;
        load_frags(0, sA, sB, 0);
        #pragma unroll
        for (int kk = 0; kk < 4; kk++) {
            if (kk < 3) load_frags((kk + 1) & 1, sA, sB, kk + 1);
            do_mma(kk & 1);
        }
    }

    // -------- epilogue: direct stores from accumulator fragments ------------
    const int mBase = bm + wm * 64;
    const int nBase = bn + wn * 32;
    #pragma unroll
    for (int mt = 0; mt < 4; mt++) {
        #pragma unroll
        for (int nt = 0; nt < 4; nt++) {
            #pragma unroll
            for (int rs = 0; rs < 2; rs++) {
                int gm = mBase + mt * 16 + (lane >> 2) + rs * 8;
                int n  = nBase + nt * 8 + 2 * (lane & 3);
                float v0 = acc[mt][nt][rs * 2 + 0];
                float v1 = acc[mt][nt][rs * 2 + 1];
                if (HID) {
                    float2 bb = *(const float2*)(bias + n);
                    float h0 = fmaxf(v0 + bb.x, 0.f), h1 = fmaxf(v1 + bb.y, 0.f);
                    __nv_bfloat16 H0 = __float2bfloat16_rn(h0);
                    __nv_bfloat16 H1 = __float2bfloat16_rn(h1);
                    __nv_bfloat16 L0 = __float2bfloat16_rn(h0 - __bfloat162float(H0));
                    __nv_bfloat16 L1 = __float2bfloat16_rn(h1 - __bfloat162float(H1));
                    __nv_bfloat162 Hh, Ll; Hh.x = H0; Hh.y = H1; Ll.x = L0; Ll.y = L1;
                    __nv_bfloat16* ob = (__nv_bfloat16*)outp + (size_t)gm * K2 + n;
                    *(__nv_bfloat162*)(ob)          = Hh;
                    *(__nv_bfloat162*)(ob + NH)     = Ll;
                    *(__nv_bfloat162*)(ob + 2 * NH) = Hh;
                } else if (n < Nrows) {
                    float2 bb = *(const float2*)(bias + n);
                    *(float2*)((float*)outp + (size_t)gm * NC + n) =
                        make_float2(v0 + bb.x, v1 + bb.y);
                }
            }
        }
    }
}

// ------- 6. fused tail: scalar head MSE + log-softmax CE + argmax per row ---
__global__ void k_tail(const float* __restrict__ Ws,
                       const float* __restrict__ bs,
                       const float* __restrict__ tgt_s,
                       const int* __restrict__ tgt_v) {
    int b = blockIdx.x, tid = threadIdx.x;   // 256 threads

    // phase 1: scalar head dot product over hidden (hi+lo from hcat)
    const __nv_bfloat16* hrow = g_hcat + (size_t)b * K2;
    float a = 0.f;
    for (int h = tid; h < NH; h += 256) {
        float hv = __bfloat162float(hrow[h]) + __bfloat162float(hrow[NH + h]);
        a += hv * Ws[h];
    }
    for (int o = 16; o; o >>= 1) a += __shfl_down_sync(0xffffffffu, a, o);
    __shared__ float sred[8];
    if ((tid & 31) == 0) sred[tid >> 5] = a;
    __syncthreads();
    if (tid == 0) {
        float t = 0.f;
        for (int w = 0; w < 8; w++) t += sred[w];
        float d = t + bs[0] - tgt_s[b];
        g_rowsq[b] = d * d;
    }
    __syncthreads();

    // phase 2: softmax CE + argmax over logits
    const float* row = g_logits + (size_t)b * NC;
    float vmax = -INFINITY; int vidx = 0x7fffffff;
    for (int c = tid; c < NC; c += 256) {
        float v = row[c];
        if (v > vmax) { vmax = v; vidx = c; }
    }
    for (int o = 16; o; o >>= 1) {
        float ov = __shfl_down_sync(0xffffffffu, vmax, o);
        int   oi = __shfl_down_sync(0xffffffffu, vidx, o);
        if (ov > vmax || (ov == vmax && oi < vidx)) { vmax = ov; vidx = oi; }
    }
    __shared__ float sv[8]; __shared__ int si[8];
    if ((tid & 31) == 0) { sv[tid >> 5] = vmax; si[tid >> 5] = vidx; }
    __syncthreads();
    __shared__ float bmax_s; __shared__ int bidx_s;
    if (tid == 0) {
        float m = sv[0]; int ix = si[0];
        for (int w = 1; w < 8; w++)
            if (sv[w] > m || (sv[w] == m && si[w] < ix)) { m = sv[w]; ix = si[w]; }
        bmax_s = m; bidx_s = ix;
    }
    __syncthreads();
    float bmax = bmax_s;
    float se = 0.f;
    for (int c = tid; c < NC; c += 256) se += expf(row[c] - bmax);
    for (int o = 16; o; o >>= 1) se += __shfl_down_sync(0xffffffffu, se, o);
    if ((tid & 31) == 0) sred[tid >> 5] = se;
    __syncthreads();
    if (tid == 0) {
        float tot = 0.f;
        for (int w = 0; w < 8; w++) tot += sred[w];
        int t = tgt_v[b];
        g_rowloss[b] = -(row[t] - bmax - logf(tot));
        g_rowcorrect[b] = (bidx_s == t) ? 1.0f : 0.0f;
    }
}

// ------- 7. final reduce ----------------------------------------------------
__global__ void k_final(float* __restrict__ out) {
    int tid = threadIdx.x;
    float l = 0.f, c = 0.f, q = 0.f;
    for (int i = tid; i < NB; i += 1024) {
        l += g_rowloss[i]; c += g_rowcorrect[i]; q += g_rowsq[i];
    }
    __shared__ float sl[1024], sc[1024], sq[1024];
    sl[tid] = l; sc[tid] = c; sq[tid] = q;
    __syncthreads();
    for (int off = 512; off > 0; off >>= 1) {
        if (tid < off) {
            sl[tid] += sl[tid + off];
            sc[tid] += sc[tid + off];
            sq[tid] += sq[tid + off];
        }
        __syncthreads();
    }
    if (tid == 0) {
        float lv = sl[0] / (float)NB;
        float ls = sq[0] / (float)NB;
        out[0] = lv + ls;
        out[1] = lv;
        out[2] = ls;
        out[3] = sc[0] / (float)NB;
    }
}

// ---------------- launch ----------------------------------------------------
extern "C" void kernel_launch(void* const* d_in, const int* in_sizes, int n_in,
                              void* d_out, int out_size) {
    const float* feature = (const float*)d_in[0];
    const float* var_flat = (const float*)d_in[1];
    const int*   seg      = (const int*)d_in[2];
    const int*   tgt_vec  = (const int*)d_in[3];
    const float* tgt_sca  = (const float*)d_in[4];
    const float* Wv = (const float*)d_in[5];
    const float* bv = (const float*)d_in[6];
    const float* W1 = (const float*)d_in[7];
    const float* b1 = (const float*)d_in[8];
    const float* W2 = (const float*)d_in[9];
    const float* b2 = (const float*)d_in[10];
    const float* Ws = (const float*)d_in[11];
    const float* bs = (const float*)d_in[12];
    float* out = (float*)d_out;
    int T = in_sizes[1] / NF;

    __nv_bfloat16 *acat1_p, *w1cat_p, *hcat_p, *w2cat_p;
    float* logits_p;
    cudaGetSymbolAddress((void**)&acat1_p, g_acat1);
    cudaGetSymbolAddress((void**)&w1cat_p, g_w1cat);
    cudaGetSymbolAddress((void**)&hcat_p, g_hcat);
    cudaGetSymbolAddress((void**)&w2cat_p, g_w2cat);
    cudaGetSymbolAddress((void**)&logits_p, g_logits);

    const int SMEMG = 3 * 32768 + 1024;    // 3-stage ring + align slack
    cudaFuncSetAttribute(k_gemm_mma<true>,
                         cudaFuncAttributeMaxDynamicSharedMemorySize, SMEMG);
    cudaFuncSetAttribute(k_gemm_mma<false>,
                         cudaFuncAttributeMaxDynamicSharedMemorySize, SMEMG);

    k_starts<<<(NB + 1 + 255) / 256, 256>>>(seg, T);
    k_means<<<NB, 256>>>(var_flat);
    k_cvt_w<<<(NH * (ND / 4) + 255) / 256, 256>>>(W1, w1cat_p, NH, ND);
    k_cvt_w<<<(NC * (NH / 4) + 255) / 256, 256>>>(W2, w2cat_p, NC, NH);
    {
        dim3 g(ND / 64, NB / 128);
        k_combined<<<g, 256>>>(feature, Wv, bv);
    }
    {   // hidden = relu(combined @ W1^T + b1) -> hcat (A-pattern)
        dim3 g(NH / 128, NB / 128);
        k_gemm_mma<true><<<g, 256, SMEMG>>>(acat1_p, w1cat_p, b1, hcat_p,
                                            K1, NH, K1 / 64);
    }
    {   // logits = hidden @ W2^T + b2
        dim3 g(1024 / 128, NB / 128);
        k_gemm_mma<false><<<g, 256, SMEMG>>>(hcat_p, w2cat_p, b2, logits_p,
                                             K2, NC, K2 / 64);
    }
    k_tail<<<NB, 256>>>(Ws, bs, tgt_sca, tgt_vec);
    k_final<<<1, 1024>>>(out);
}

// round 11
// speedup vs baseline: 3.4843x; 1.3508x over previous
#include <cuda_runtime.h>
#include <cuda_fp16.h>
#include <math.h>
#include <stdint.h>

#define NB 4096
#define ND 1024
#define NH 2048
#define NC 1000
#define NF 32
#define K1N (2*ND)   // 2048 split-cat K for GEMM1 (fp16 2-term)
#define K2N (2*NH)   // 4096 split-cat K for GEMM2

// ---------------- scratch ---------------------------------------------------
__device__ float g_means[NB * NF];
__device__ __align__(16) __half g_acat1[(size_t)NB * K1N];  // A: [hi, lo]
__device__ __align__(16) __half g_w1cat[(size_t)NH * K1N];  // B: [hi, hi]
__device__ __align__(16) __half g_hcat[(size_t)NB * K2N];   // A: [hi, lo]
__device__ __align__(16) __half g_w2cat[(size_t)NC * K2N];  // B: [hi, hi]
__device__ float g_logits[(size_t)NB * NC];
__device__ float g_rowloss[NB];
__device__ float g_rowcorrect[NB];
__device__ float g_rowsq[NB];
__device__ int   g_starts[NB + 1];

// ---------------- helpers ---------------------------------------------------
__device__ __forceinline__ uint32_t smem_u32(const void* p) {
    uint32_t a;
    asm("{ .reg .u64 t; cvta.to.shared.u64 t, %1; cvt.u32.u64 %0, t; }"
        : "=r"(a) : "l"(p));
    return a;
}

__device__ __forceinline__ void ldsm4(uint32_t& r0, uint32_t& r1, uint32_t& r2,
                                      uint32_t& r3, uint32_t a) {
    asm volatile("ldmatrix.sync.aligned.m8n8.x4.shared.b16 {%0,%1,%2,%3}, [%4];"
                 : "=r"(r0), "=r"(r1), "=r"(r2), "=r"(r3) : "r"(a));
}

__device__ __forceinline__ void mma16816(float* c, uint32_t a0, uint32_t a1,
                                         uint32_t a2, uint32_t a3,
                                         uint32_t b0, uint32_t b1) {
    asm volatile(
        "mma.sync.aligned.m16n8k16.row.col.f32.f16.f16.f32 "
        "{%0,%1,%2,%3}, {%4,%5,%6,%7}, {%8,%9}, {%0,%1,%2,%3};"
        : "+f"(c[0]), "+f"(c[1]), "+f"(c[2]), "+f"(c[3])
        : "r"(a0), "r"(a1), "r"(a2), "r"(a3), "r"(b0), "r"(b1));
}

#define CPA16(sa, ga, pbytes) \
    asm volatile("cp.async.cg.shared.global [%0], [%1], 16, %2;" \
                 :: "r"(sa), "l"(ga), "r"(pbytes))
#define CPA_COMMIT() asm volatile("cp.async.commit_group;" ::: "memory")

// ---------------- 1. segment starts -----------------------------------------
__global__ void k_starts(const int* __restrict__ seg, int T) {
    int b = blockIdx.x * blockDim.x + threadIdx.x;
    if (b > NB) return;
    int lo = 0, hi = T;
    while (lo < hi) { int m = (lo + hi) >> 1; if (seg[m] < b) lo = m + 1; else hi = m; }
    g_starts[b] = lo;
}

// ---------------- 2. per-segment mean ---------------------------------------
__global__ void k_means(const float* __restrict__ vf) {
    int b = blockIdx.x;
    int start = g_starts[b], end = g_starts[b + 1];
    int tid = threadIdx.x;
    int j = tid & 7, r = tid >> 3;
    float4 acc = make_float4(0.f, 0.f, 0.f, 0.f);
    for (int row = start + r; row < end; row += 32) {
        float4 v = *(const float4*)(vf + (size_t)row * NF + j * 4);
        acc.x += v.x; acc.y += v.y; acc.z += v.z; acc.w += v.w;
    }
    __shared__ float4 s[256];
    s[tid] = acc; __syncthreads();
    for (int off = 128; off >= 8; off >>= 1) {
        if (tid < off) {
            float4 o = s[tid + off]; float4 m = s[tid];
            m.x += o.x; m.y += o.y; m.z += o.z; m.w += o.w; s[tid] = m;
        }
        __syncthreads();
    }
    if (tid < 8) {
        float inv = 1.0f / fmaxf((float)(end - start), 1.0f);
        float4 m = s[tid];
        m.x *= inv; m.y *= inv; m.z *= inv; m.w *= inv;
        *(float4*)(g_means + (size_t)b * NF + tid * 4) = m;
    }
}

// ------- 3. weight fp32 -> fp16 hi, duplicated B-pattern [hi, hi] -----------
__global__ void k_cvt_w(const float* __restrict__ W, __half* __restrict__ out,
                        int R, int K) {
    int q = K >> 2;
    int idx = blockIdx.x * blockDim.x + threadIdx.x;
    if (idx >= R * q) return;
    int r = idx / q;
    int c = (idx - r * q) * 4;
    float4 v = *(const float4*)(W + (size_t)r * K + c);
    union { __half h[4]; uint2 u; } H;
    H.h[0] = __float2half_rn(v.x); H.h[1] = __float2half_rn(v.y);
    H.h[2] = __float2half_rn(v.z); H.h[3] = __float2half_rn(v.w);
    __half* ob = out + (size_t)r * (2 * K) + c;
    *(uint2*)(ob)     = H.u;
    *(uint2*)(ob + K) = H.u;
}

// ------- 4. combined = feature + means @ Wv^T + bv -> A-pattern [hi, lo] ----
__global__ void k_combined(const float* __restrict__ feat,
                           const float* __restrict__ Wv,
                           const float* __restrict__ bv) {
    __shared__ float wv_s[NF][64];
    __shared__ float me_s[NF][128];
    int d0 = blockIdx.x * 64, b0 = blockIdx.y * 128;
    int tid = threadIdx.x;
    for (int idx = tid; idx < 64 * 8; idx += 256) {
        int dd = idx >> 3, fg = (idx & 7) * 4;
        float4 v = *(const float4*)(Wv + (size_t)(d0 + dd) * NF + fg);
        wv_s[fg + 0][dd] = v.x; wv_s[fg + 1][dd] = v.y;
        wv_s[fg + 2][dd] = v.z; wv_s[fg + 3][dd] = v.w;
    }
    for (int idx = tid; idx < 128 * 8; idx += 256) {
        int bb = idx >> 3, fg = (idx & 7) * 4;
        float4 v = *(const float4*)(g_means + (size_t)(b0 + bb) * NF + fg);
        me_s[fg + 0][bb] = v.x; me_s[fg + 1][bb] = v.y;
        me_s[fg + 2][bb] = v.z; me_s[fg + 3][bb] = v.w;
    }
    __syncthreads();
    int tx = tid & 15, ty = tid >> 4;
    float acc[8][4];
    #pragma unroll
    for (int r = 0; r < 8; r++)
        #pragma unroll
        for (int c = 0; c < 4; c++) acc[r][c] = 0.f;
    #pragma unroll 4
    for (int f = 0; f < NF; f++) {
        float w[4], m[8];
        #pragma unroll
        for (int c = 0; c < 4; c++) w[c] = wv_s[f][tx * 4 + c];
        #pragma unroll
        for (int r = 0; r < 8; r++) m[r] = me_s[f][ty * 8 + r];
        #pragma unroll
        for (int r = 0; r < 8; r++)
            #pragma unroll
            for (int c = 0; c < 4; c++) acc[r][c] += m[r] * w[c];
    }
    int d = d0 + tx * 4;
    float4 bvv = *(const float4*)(bv + d);
    #pragma unroll
    for (int r = 0; r < 8; r++) {
        int b = b0 + ty * 8 + r;
        float4 fv = *(const float4*)(feat + (size_t)b * ND + d);
        float o[4] = { fv.x + bvv.x + acc[r][0], fv.y + bvv.y + acc[r][1],
                       fv.z + bvv.z + acc[r][2], fv.w + bvv.w + acc[r][3] };
        __half* ob = g_acat1 + (size_t)b * K1N + d;
        #pragma unroll
        for (int p = 0; p < 2; p++) {
            __half h0 = __float2half_rn(o[p * 2]);
            __half h1 = __float2half_rn(o[p * 2 + 1]);
            __half l0 = __float2half_rn(o[p * 2] - __half2float(h0));
            __half l1 = __float2half_rn(o[p * 2 + 1] - __half2float(h1));
            __half2 H, L; H.x = h0; H.y = h1; L.x = l0; L.y = l1;
            *(__half2*)(ob + p * 2)      = H;
            *(__half2*)(ob + ND + p * 2) = L;
        }
    }
}

// ------- 5. fp16 mma.sync GEMM: C = A @ B^T (+bias; relu+split / fp32) ------
// Block 256x128, 8 warps 4(m)x2(n), warp tile 64x64, 3-stage cp.async ring.
template <bool HID>
__global__ void __launch_bounds__(256, 1)
k_gemm_mma(const __half* __restrict__ A, const __half* __restrict__ B,
           const float* __restrict__ bias, void* __restrict__ outp,
           int Kp, int Nrows, int NK) {
    extern __shared__ char dsm[];
    uint32_t raw = smem_u32(dsm);
    const uint32_t sm0 = (raw + 1023u) & ~1023u;

    const int tid = threadIdx.x, wid = tid >> 5, lane = tid & 31;
    const int wm = wid >> 1, wn = wid & 1;
    const int bm = blockIdx.y * 256, bn = blockIdx.x * 128;
    const size_t rowb = (size_t)Kp * 2;

    const int lrow0 = tid >> 3;
    const int ls    = tid & 7;
    const uint32_t lsw = (uint32_t)((ls * 16) ^ ((lrow0 & 7) * 16));

    // stage: A 256x128B = 32KB, B 128x128B = 16KB -> 48KB
    auto load_stage = [&](int slot, int kt) {
        uint32_t sb = sm0 + slot * 49152;
        int k0b = kt * 128;
        #pragma unroll
        for (int i = 0; i < 8; i++) {
            int r = lrow0 + i * 32;
            uint32_t sa = sb + r * 128 + lsw;
            const char* g = (const char*)A + (size_t)(bm + r) * rowb + k0b + ls * 16;
            CPA16(sa, g, 16);
        }
        #pragma unroll
        for (int i = 0; i < 4; i++) {
            int r = lrow0 + i * 32;
            int gr = bn + r;
            bool v = gr < Nrows;
            uint32_t sa = sb + 32768 + r * 128 + lsw;
            const char* g = (const char*)B + (size_t)(v ? gr : 0) * rowb + k0b + ls * 16;
            CPA16(sa, g, v ? 16 : 0);
        }
        CPA_COMMIT();
    };

    const int aRow = wm * 64 + (lane & 15);
    const uint32_t cbA  = (uint32_t)((lane >> 4) * 16);
    const uint32_t xorA = (uint32_t)((lane & 7) * 16);
    const int bRow = wn * 64 + (lane & 7) + ((lane >> 4) << 3);
    const uint32_t cbB  = (uint32_t)(((lane >> 3) & 1) * 16);
    const uint32_t xorB = (uint32_t)((lane & 7) * 16);

    float acc[4][8][4];
    #pragma unroll
    for (int i = 0; i < 4; i++)
        #pragma unroll
        for (int j = 0; j < 8; j++)
            #pragma unroll
            for (int k = 0; k < 4; k++) acc[i][j][k] = 0.f;

    uint32_t af[4][4], bf[4][4];

    load_stage(0, 0); load_stage(1, 1);

    #pragma unroll 1
    for (int ks = 0; ks < NK; ks++) {
        int slot = ks - (ks / 3) * 3;
        asm volatile("cp.async.wait_group 1;" ::: "memory");
        __syncthreads();
        if (ks + 2 < NK) {
            int s2 = (ks + 2) - ((ks + 2) / 3) * 3;
            load_stage(s2, ks + 2);
        }
        uint32_t sA = sm0 + slot * 49152;
        uint32_t sB = sA + 32768;
        #pragma unroll
        for (int kk = 0; kk < 4; kk++) {
            #pragma unroll
            for (int mt = 0; mt < 4; mt++)
                ldsm4(af[mt][0], af[mt][1], af[mt][2], af[mt][3],
                      sA + (uint32_t)(aRow + mt * 16) * 128 +
                          (((uint32_t)(32 * kk) + cbA) ^ xorA));
            #pragma unroll
            for (int nt2 = 0; nt2 < 4; nt2++)
                ldsm4(bf[nt2][0], bf[nt2][1], bf[nt2][2], bf[nt2][3],
                      sB + (uint32_t)(bRow + nt2 * 16) * 128 +
                          (((uint32_t)(32 * kk) + cbB) ^ xorB));
            #pragma unroll
            for (int mt = 0; mt < 4; mt++)
                #pragma unroll
                for (int nt2 = 0; nt2 < 4; nt2++) {
                    mma16816(acc[mt][nt2 * 2],
                             af[mt][0], af[mt][1], af[mt][2], af[mt][3],
                             bf[nt2][0], bf[nt2][1]);
                    mma16816(acc[mt][nt2 * 2 + 1],
                             af[mt][0], af[mt][1], af[mt][2], af[mt][3],
                             bf[nt2][2], bf[nt2][3]);
                }
        }
    }

    // -------- epilogue: direct stores from accumulator fragments ------------
    const int mBase = bm + wm * 64;
    const int nBase = bn + wn * 64;
    #pragma unroll
    for (int mt = 0; mt < 4; mt++) {
        #pragma unroll
        for (int nt = 0; nt < 8; nt++) {
            #pragma unroll
            for (int rs = 0; rs < 2; rs++) {
                int gm = mBase + mt * 16 + (lane >> 2) + rs * 8;
                int n  = nBase + nt * 8 + 2 * (lane & 3);
                float v0 = acc[mt][nt][rs * 2 + 0];
                float v1 = acc[mt][nt][rs * 2 + 1];
                if (HID) {
                    float2 bb = *(const float2*)(bias + n);
                    float h0 = fmaxf(v0 + bb.x, 0.f), h1 = fmaxf(v1 + bb.y, 0.f);
                    __half H0 = __float2half_rn(h0), H1 = __float2half_rn(h1);
                    __half L0 = __float2half_rn(h0 - __half2float(H0));
                    __half L1 = __float2half_rn(h1 - __half2float(H1));
                    __half2 Hh, Ll; Hh.x = H0; Hh.y = H1; Ll.x = L0; Ll.y = L1;
                    __half* ob = (__half*)outp + (size_t)gm * K2N + n;
                    *(__half2*)(ob)      = Hh;
                    *(__half2*)(ob + NH) = Ll;
                } else if (n < Nrows) {
                    float2 bb = *(const float2*)(bias + n);
                    *(float2*)((float*)outp + (size_t)gm * NC + n) =
                        make_float2(v0 + bb.x, v1 + bb.y);
                }
            }
        }
    }
}

// ------- 6. fused tail: scalar head MSE + log-softmax CE + argmax per row ---
__global__ void k_tail(const float* __restrict__ Ws,
                       const float* __restrict__ bs,
                       const float* __restrict__ tgt_s,
                       const int* __restrict__ tgt_v) {
    int b = blockIdx.x, tid = threadIdx.x;   // 256 threads

    const __half* hrow = g_hcat + (size_t)b * K2N;
    float a = 0.f;
    for (int h = tid; h < NH; h += 256) {
        float hv = __half2float(hrow[h]) + __half2float(hrow[NH + h]);
        a += hv * Ws[h];
    }
    for (int o = 16; o; o >>= 1) a += __shfl_down_sync(0xffffffffu, a, o);
    __shared__ float sred[8];
    if ((tid & 31) == 0) sred[tid >> 5] = a;
    __syncthreads();
    if (tid == 0) {
        float t = 0.f;
        for (int w = 0; w < 8; w++) t += sred[w];
        float d = t + bs[0] - tgt_s[b];
        g_rowsq[b] = d * d;
    }
    __syncthreads();

    const float* row = g_logits + (size_t)b * NC;
    float vmax = -INFINITY; int vidx = 0x7fffffff;
    for (int c = tid; c < NC; c += 256) {
        float v = row[c];
        if (v > vmax) { vmax = v; vidx = c; }
    }
    for (int o = 16; o; o >>= 1) {
        float ov = __shfl_down_sync(0xffffffffu, vmax, o);
        int   oi = __shfl_down_sync(0xffffffffu, vidx, o);
        if (ov > vmax || (ov == vmax && oi < vidx)) { vmax = ov; vidx = oi; }
    }
    __shared__ float sv[8]; __shared__ int si[8];
    if ((tid & 31) == 0) { sv[tid >> 5] = vmax; si[tid >> 5] = vidx; }
    __syncthreads();
    __shared__ float bmax_s; __shared__ int bidx_s;
    if (tid == 0) {
        float m = sv[0]; int ix = si[0];
        for (int w = 1; w < 8; w++)
            if (sv[w] > m || (sv[w] == m && si[w] < ix)) { m = sv[w]; ix = si[w]; }
        bmax_s = m; bidx_s = ix;
    }
    __syncthreads();
    float bmax = bmax_s;
    float se = 0.f;
    for (int c = tid; c < NC; c += 256) se += expf(row[c] - bmax);
    for (int o = 16; o; o >>= 1) se += __shfl_down_sync(0xffffffffu, se, o);
    if ((tid & 31) == 0) sred[tid >> 5] = se;
    __syncthreads();
    if (tid == 0) {
        float tot = 0.f;
        for (int w = 0; w < 8; w++) tot += sred[w];
        int t = tgt_v[b];
        g_rowloss[b] = -(row[t] - bmax - logf(tot));
        g_rowcorrect[b] = (bidx_s == t) ? 1.0f : 0.0f;
    }
}

// ------- 7. final reduce ----------------------------------------------------
__global__ void k_final(float* __restrict__ out) {
    int tid = threadIdx.x;
    float l = 0.f, c = 0.f, q = 0.f;
    for (int i = tid; i < NB; i += 1024) {
        l += g_rowloss[i]; c += g_rowcorrect[i]; q += g_rowsq[i];
    }
    __shared__ float sl[1024], sc[1024], sq[1024];
    sl[tid] = l; sc[tid] = c; sq[tid] = q;
    __syncthreads();
    for (int off = 512; off > 0; off >>= 1) {
        if (tid < off) {
            sl[tid] += sl[tid + off];
            sc[tid] += sc[tid + off];
            sq[tid] += sq[tid + off];
        }
        __syncthreads();
    }
    if (tid == 0) {
        float lv = sl[0] / (float)NB;
        float ls = sq[0] / (float)NB;
        out[0] = lv + ls;
        out[1] = lv;
        out[2] = ls;
        out[3] = sc[0] / (float)NB;
    }
}

// ---------------- launch ----------------------------------------------------
extern "C" void kernel_launch(void* const* d_in, const int* in_sizes, int n_in,
                              void* d_out, int out_size) {
    const float* feature = (const float*)d_in[0];
    const float* var_flat = (const float*)d_in[1];
    const int*   seg      = (const int*)d_in[2];
    const int*   tgt_vec  = (const int*)d_in[3];
    const float* tgt_sca  = (const float*)d_in[4];
    const float* Wv = (const float*)d_in[5];
    const float* bv = (const float*)d_in[6];
    const float* W1 = (const float*)d_in[7];
    const float* b1 = (const float*)d_in[8];
    const float* W2 = (const float*)d_in[9];
    const float* b2 = (const float*)d_in[10];
    const float* Ws = (const float*)d_in[11];
    const float* bs = (const float*)d_in[12];
    float* out = (float*)d_out;
    int T = in_sizes[1] / NF;

    __half *acat1_p, *w1cat_p, *hcat_p, *w2cat_p;
    float* logits_p;
    cudaGetSymbolAddress((void**)&acat1_p, g_acat1);
    cudaGetSymbolAddress((void**)&w1cat_p, g_w1cat);
    cudaGetSymbolAddress((void**)&hcat_p, g_hcat);
    cudaGetSymbolAddress((void**)&w2cat_p, g_w2cat);
    cudaGetSymbolAddress((void**)&logits_p, g_logits);

    const int SMEMG = 3 * 49152 + 1024;    // 3-stage 48KB ring + align slack
    cudaFuncSetAttribute(k_gemm_mma<true>,
                         cudaFuncAttributeMaxDynamicSharedMemorySize, SMEMG);
    cudaFuncSetAttribute(k_gemm_mma<false>,
                         cudaFuncAttributeMaxDynamicSharedMemorySize, SMEMG);

    k_starts<<<(NB + 1 + 255) / 256, 256>>>(seg, T);
    k_means<<<NB, 256>>>(var_flat);
    k_cvt_w<<<(NH * (ND / 4) + 255) / 256, 256>>>(W1, w1cat_p, NH, ND);
    k_cvt_w<<<(NC * (NH / 4) + 255) / 256, 256>>>(W2, w2cat_p, NC, NH);
    {
        dim3 g(ND / 64, NB / 128);
        k_combined<<<g, 256>>>(feature, Wv, bv);
    }
    {   // hidden = relu(combined @ W1^T + b1) -> hcat [hi, lo]
        dim3 g(NH / 128, NB / 256);
        k_gemm_mma<true><<<g, 256, SMEMG>>>(acat1_p, w1cat_p, b1, hcat_p,
                                            K1N, NH, K1N / 64);
    }
    {   // logits = hidden @ W2^T + b2
        dim3 g(1024 / 128, NB / 256);
        k_gemm_mma<false><<<g, 256, SMEMG>>>(hcat_p, w2cat_p, b2, logits_p,
                                             K2N, NC, K2N / 64);
    }
    k_tail<<<NB, 256>>>(Ws, bs, tgt_sca, tgt_vec);
    k_final<<<1, 1024>>>(out);
}